// round 14
// baseline (speedup 1.0000x reference)
#include <cuda_runtime.h>
#include <math.h>
#include <stdint.h>

#define NNODE 100000
#define EDGES 800000
#define DIN   128
#define HDIM  256
#define NB    98          // scan blocks per side: ceil(100000/1024)

// ---------------------------------------------------------------------------
// Scratch (__device__ globals; no allocation allowed)
// ---------------------------------------------------------------------------
__device__ float g_hu [(size_t)NNODE * HDIM];
__device__ float g_hi [(size_t)NNODE * HDIM];
__device__ float g_tu [(size_t)NNODE * HDIM];
__device__ float g_ti [(size_t)NNODE * HDIM];
__device__ float g_agg[2 * (size_t)NNODE * HDIM];   // agg0 | agg1
__device__ int   g_deg[2 * NNODE];
__device__ int   g_off[2 * NNODE];
__device__ int   g_cur[2 * NNODE];
__device__ int   g_csr[2 * EDGES];
__device__ int   g_bsum[2 * NB];
__device__ int   g_bpre[2 * NB];
__device__ float g_wts[2 * 32768 + 10 * 65536];     // tf32 TRANSPOSED weights

// ---------------------------------------------------------------------------
// Helpers
// ---------------------------------------------------------------------------
__device__ __forceinline__ float gelu_f(float x) {
    return 0.5f * x * (1.0f + erff(x * 0.70710678118654752f));
}
__device__ __forceinline__ float to_tf32(float x) {
    float r;
    asm("cvt.rna.tf32.f32 %0, %1;" : "=f"(r) : "f"(x));
    return r;
}
__device__ __forceinline__ uint32_t cvt_u(uint32_t x) {
    return __float_as_uint(to_tf32(__uint_as_float(x)));
}
__device__ __forceinline__ void mma_tf32(float& d0, float& d1, float& d2, float& d3,
                                         uint32_t a0, uint32_t a1, uint32_t a2, uint32_t a3,
                                         uint32_t b0, uint32_t b1)
{
    asm volatile(
        "mma.sync.aligned.m16n8k8.row.col.f32.tf32.tf32.f32 "
        "{%0,%1,%2,%3}, {%4,%5,%6,%7}, {%8,%9}, {%0,%1,%2,%3};"
        : "+f"(d0), "+f"(d1), "+f"(d2), "+f"(d3)
        : "r"(a0), "r"(a1), "r"(a2), "r"(a3), "r"(b0), "r"(b1));
}
__device__ __forceinline__ void cp16(uint32_t dst, const void* src, bool pred) {
    int sz = pred ? 16 : 0;
    asm volatile("cp.async.ca.shared.global [%0], [%1], 16, %2;"
                 :: "r"(dst), "l"(src), "r"(sz));
}
__device__ __forceinline__ void ldsm4(uint32_t& r0, uint32_t& r1, uint32_t& r2, uint32_t& r3,
                                      uint32_t addr)
{
    asm volatile("ldmatrix.sync.aligned.m8n8.x4.shared.b16 {%0,%1,%2,%3}, [%4];"
                 : "=r"(r0), "=r"(r1), "=r"(r2), "=r"(r3) : "r"(addr));
}

// ---------------------------------------------------------------------------
// CSR structs
// ---------------------------------------------------------------------------
struct EdgePair {
    const int* src[2];
    const int* dst[2];
    int*       deg[2];
    int*       off[2];
    int*       cur[2];
    int*       csr[2];
};

// ---------------------------------------------------------------------------
// Merged prologue: weight transpose-convert (y < NTW) + degree count (y >= NTW)
// ---------------------------------------------------------------------------
#define NTW 12
struct TPack { const float* src[NTW]; float* dst[NTW]; int K[NTW]; };

__global__ void __launch_bounds__(256)
prologue_kernel(TPack p, EdgePair ep, int nE)
{
    int m = blockIdx.y;
    if (m < NTW) {
        // 32x32 smem-tile transpose; only first 64 (or 32 for K=128) x-blocks do work
        int K = p.K[m];
        int kt = (blockIdx.x & 7) * 32;
        int nt = (blockIdx.x >> 3) * 32;
        if (blockIdx.x >= 64 || kt >= K) return;
        __shared__ float tile[32][33];
        const float* __restrict__ s = p.src[m];
        float*       __restrict__ d = p.dst[m];
        int tx = threadIdx.x & 31;
        int ty = threadIdx.x >> 5;
        #pragma unroll
        for (int u = 0; u < 4; u++) {
            int r = ty + u * 8;
            tile[r][tx] = to_tf32(s[(size_t)(kt + r) * 256 + nt + tx]);
        }
        __syncthreads();
        #pragma unroll
        for (int u = 0; u < 4; u++) {
            int r = ty + u * 8;
            d[(size_t)(nt + r) * K + kt + tx] = tile[tx][r];
        }
    } else {
        int z = m - NTW;
        const int* __restrict__ dst = ep.dst[z];
        int* __restrict__ deg = ep.deg[z];
        for (int i = blockIdx.x * blockDim.x + threadIdx.x; i < nE;
             i += gridDim.x * blockDim.x)
            atomicAdd(&deg[dst[i]], 1);
    }
}

// ---------------------------------------------------------------------------
// Multi-block scan
// ---------------------------------------------------------------------------
__global__ void __launch_bounds__(256)
bsum_pair_kernel(EdgePair p, int n, int* __restrict__ bsum)
{
    int z = blockIdx.y;
    int b = blockIdx.x;
    int t = threadIdx.x;
    int base = b * 1024;
    int s = 0;
    #pragma unroll
    for (int u = 0; u < 4; u++) {
        int i = base + t + u * 256;
        if (i < n) s += p.deg[z][i];
    }
    #pragma unroll
    for (int m = 16; m > 0; m >>= 1) s += __shfl_xor_sync(0xffffffffu, s, m);
    __shared__ int ws[8];
    if ((t & 31) == 0) ws[t >> 5] = s;
    __syncthreads();
    if (t < 8) {
        int v = ws[t];
        #pragma unroll
        for (int m = 4; m > 0; m >>= 1) v += __shfl_xor_sync(0xffu, v, m);
        if (t == 0) bsum[z * NB + b] = v;
    }
}

__global__ void __launch_bounds__(32)
bscan_kernel(const int* __restrict__ bsum, int* __restrict__ bpre)
{
    int z = threadIdx.x;
    if (z < 2) {
        int acc = 0;
        for (int b = 0; b < NB; b++) {
            bpre[z * NB + b] = acc;
            acc += bsum[z * NB + b];
        }
    }
}

__global__ void __launch_bounds__(1024)
addoff_pair_kernel(EdgePair p, int n, const int* __restrict__ bpre)
{
    int z = blockIdx.y;
    int b = blockIdx.x;
    int i = b * 1024 + threadIdx.x;
    int lane = threadIdx.x & 31;
    int wid  = threadIdx.x >> 5;
    int v = (i < n) ? p.deg[z][i] : 0;
    int x = v;
    #pragma unroll
    for (int s = 1; s < 32; s <<= 1) {
        int y = __shfl_up_sync(0xffffffffu, x, s);
        if (lane >= s) x += y;
    }
    __shared__ int ws[32];
    if (lane == 31) ws[wid] = x;
    __syncthreads();
    if (wid == 0) {
        int w = ws[lane];
        #pragma unroll
        for (int s = 1; s < 32; s <<= 1) {
            int y = __shfl_up_sync(0xffffffffu, w, s);
            if (lane >= s) w += y;
        }
        ws[lane] = w;
    }
    __syncthreads();
    int excl = x - v + (wid > 0 ? ws[wid - 1] : 0) + bpre[z * NB + b];
    if (i < n) { p.off[z][i] = excl; p.cur[z][i] = excl; }
}

__global__ void __launch_bounds__(256)
csr_pair_kernel(EdgePair p, int nE)
{
    int z = blockIdx.y;
    int e = blockIdx.x * blockDim.x + threadIdx.x;
    if (e >= nE) return;
    int pos = atomicAdd(&p.cur[z][p.dst[z][e]], 1);
    p.csr[z][pos] = p.src[z][e];
}

// ---------------------------------------------------------------------------
// Paired CSR aggregation
// ---------------------------------------------------------------------------
struct AggPair {
    const float* h[2];
    const int*   csr[2];
    const int*   off[2];
    const int*   deg[2];
    float*       agg[2];
};

__global__ void __launch_bounds__(256)
agg_pair_kernel(AggPair p, int n)
{
    int node = blockIdx.x * 8 + (threadIdx.x >> 5);
    if (node >= n) return;
    const int z = blockIdx.z;
    const float* __restrict__ h   = p.h[z];
    const int*   __restrict__ csr = p.csr[z];
    float*       __restrict__ agg = p.agg[z];
    int coff = blockIdx.y * 128;
    int lane = threadIdx.x & 31;
    int o = __ldg(&p.off[z][node]);
    int d = __ldg(&p.deg[z][node]);
    float4 acc = make_float4(0.f, 0.f, 0.f, 0.f);
    int j = 0;
    for (; j + 4 <= d; j += 4) {
        int s0 = __ldg(&csr[o + j]);
        int s1 = __ldg(&csr[o + j + 1]);
        int s2 = __ldg(&csr[o + j + 2]);
        int s3 = __ldg(&csr[o + j + 3]);
        float4 v0 = *reinterpret_cast<const float4*>(h + (size_t)s0 * HDIM + coff + lane * 4);
        float4 v1 = *reinterpret_cast<const float4*>(h + (size_t)s1 * HDIM + coff + lane * 4);
        float4 v2 = *reinterpret_cast<const float4*>(h + (size_t)s2 * HDIM + coff + lane * 4);
        float4 v3 = *reinterpret_cast<const float4*>(h + (size_t)s3 * HDIM + coff + lane * 4);
        acc.x += v0.x + v1.x + v2.x + v3.x;
        acc.y += v0.y + v1.y + v2.y + v3.y;
        acc.z += v0.z + v1.z + v2.z + v3.z;
        acc.w += v0.w + v1.w + v2.w + v3.w;
    }
    for (; j < d; j++) {
        int s = __ldg(&csr[o + j]);
        float4 v = *reinterpret_cast<const float4*>(h + (size_t)s * HDIM + coff + lane * 4);
        acc.x += v.x; acc.y += v.y; acc.z += v.z; acc.w += v.w;
    }
    float sc = 1.0f / fmaxf((float)d, 1.0f);
    float4 r;
    r.x = to_tf32(acc.x * sc);
    r.y = to_tf32(acc.y * sc);
    r.z = to_tf32(acc.z * sc);
    r.w = to_tf32(acc.w * sc);
    *reinterpret_cast<float4*>(agg + (size_t)node * HDIM + coff + lane * 4) = r;
}

// ---------------------------------------------------------------------------
// Paired in-place LayerNorm
// ---------------------------------------------------------------------------
struct LnPair {
    float*       x[2];
    const float* g[2];
    const float* b[2];
};

__global__ void __launch_bounds__(256)
ln_pair_kernel(LnPair pp, int M)
{
    int row  = blockIdx.x * 8 + (threadIdx.x >> 5);
    int lane = threadIdx.x & 31;
    if (row >= M) return;
    const int z = blockIdx.y;
    float* p = pp.x[z] + (size_t)row * HDIM + lane * 8;
    const float* g = pp.g[z];
    const float* b = pp.b[z];
    float4 v0 = *reinterpret_cast<const float4*>(p);
    float4 v1 = *reinterpret_cast<const float4*>(p + 4);
    float s  = v0.x + v0.y + v0.z + v0.w + v1.x + v1.y + v1.z + v1.w;
    float sq = v0.x*v0.x + v0.y*v0.y + v0.z*v0.z + v0.w*v0.w
             + v1.x*v1.x + v1.y*v1.y + v1.z*v1.z + v1.w*v1.w;
    #pragma unroll
    for (int m = 16; m > 0; m >>= 1) {
        s  += __shfl_xor_sync(0xffffffffu, s,  m);
        sq += __shfl_xor_sync(0xffffffffu, sq, m);
    }
    float mu   = s * (1.0f / 256.0f);
    float var  = sq * (1.0f / 256.0f) - mu * mu;
    float rstd = rsqrtf(var + 1e-5f);
    float4 g0 = *reinterpret_cast<const float4*>(g + lane * 8);
    float4 g1 = *reinterpret_cast<const float4*>(g + lane * 8 + 4);
    float4 b0 = *reinterpret_cast<const float4*>(b + lane * 8);
    float4 b1 = *reinterpret_cast<const float4*>(b + lane * 8 + 4);
    float4 o0, o1;
    o0.x = (v0.x - mu) * rstd * g0.x + b0.x;
    o0.y = (v0.y - mu) * rstd * g0.y + b0.y;
    o0.z = (v0.z - mu) * rstd * g0.z + b0.z;
    o0.w = (v0.w - mu) * rstd * g0.w + b0.w;
    o1.x = (v1.x - mu) * rstd * g1.x + b1.x;
    o1.y = (v1.y - mu) * rstd * g1.y + b1.y;
    o1.z = (v1.z - mu) * rstd * g1.z + b1.z;
    o1.w = (v1.w - mu) * rstd * g1.w + b1.w;
    *reinterpret_cast<float4*>(p)     = o0;
    *reinterpret_cast<float4*>(p + 4) = o1;
}

// ---------------------------------------------------------------------------
// Paired 3-stage cp.async tf32 GEMM, 512 threads, 16 warps of 32x32 tiles.
// CVT_A: A loaded as raw fp32, fragments converted to tf32 after ldmatrix.
// ---------------------------------------------------------------------------
constexpr int BM   = 128;
constexpr int BK   = 32;
constexpr int LDT  = 36;
constexpr int TILE_B = BM * LDT * 4;
constexpr int ST   = 3;

struct GemmPair {
    const float* A1[2];
    const float* A2[2];
    const float* W1[2];   // transposed [256][K], tf32
    const float* W2[2];
    const float* bias[2];
    float*       C[2];
};

template<int K, bool HAS_A2, int EPI, bool CVT_A>
__global__ void __launch_bounds__(512, 2)
gemm_pair(GemmPair p, int M)
{
    __shared__ float a_s[ST][BM * LDT];
    __shared__ float b_s[ST][BM * LDT];

    constexpr int NIT = (HAS_A2 ? 2 : 1) * K / BK;

    const int zz = blockIdx.z;
    const float* __restrict__ A1g  = p.A1[zz];
    const float* __restrict__ A2g  = p.A2[zz];
    const float* __restrict__ W1g  = p.W1[zz];
    const float* __restrict__ W2g  = p.W2[zz];
    const float* __restrict__ bias = p.bias[zz];
    float*       __restrict__ C    = p.C[zz];

    const int tid  = threadIdx.x;
    const int lane = tid & 31;
    const int wid  = tid >> 5;          // 0..15
    const int wm   = wid >> 2;          // 0..3
    const int wn   = wid & 3;           // 0..3
    const int lq   = lane >> 2;
    const int lr   = lane & 3;
    const int row0 = blockIdx.y * BM;
    const int ncol0 = blockIdx.x * 128;

    const int ar  = tid >> 3;           // 0..63; + u*64
    const int ac4 = (tid & 7) << 2;

    const uint32_t a_base = (uint32_t)__cvta_generic_to_shared(a_s);
    const uint32_t b_base = (uint32_t)__cvta_generic_to_shared(b_s);

    const int g8 = lane >> 3;
    const int l8 = lane & 7;
    const int row_a = ((g8 & 1) << 3) + l8;
    const int col_a = (g8 >> 1) << 2;
    const uint32_t a_frag0 = a_base + (uint32_t)(((wm * 32 + row_a) * LDT + col_a) << 2);
    const int row_b = ((g8 >> 1) << 3) + l8;
    const int col_b = (g8 & 1) << 2;
    const uint32_t b_frag0 = b_base + (uint32_t)(((wn * 32 + row_b) * LDT + col_b) << 2);

    float d[2][4][4];
    #pragma unroll
    for (int i = 0; i < 2; i++)
        #pragma unroll
        for (int j = 0; j < 4; j++)
            #pragma unroll
            for (int q = 0; q < 4; q++)
                d[i][j][q] = 0.f;

    auto load_stage = [&](int kt, int buf) {
        int kk = kt * BK;
        const float* __restrict__ A  = (HAS_A2 && kk >= K) ? A2g : A1g;
        const float* __restrict__ WT = (HAS_A2 && kk >= K) ? W2g : W1g;
        const int k0 = HAS_A2 ? (kk & (K - 1)) : kk;
        uint32_t ab = a_base + (uint32_t)(buf * TILE_B);
        uint32_t bb = b_base + (uint32_t)(buf * TILE_B);
        #pragma unroll
        for (int u = 0; u < 2; u++) {
            int r  = ar + u * 64;
            int gr = row0 + r;
            int gc = gr < M ? gr : (M - 1);
            cp16(ab + (uint32_t)((r * LDT + ac4) << 2),
                 A + (size_t)gc * K + k0 + ac4, gr < M);
            cp16(bb + (uint32_t)((r * LDT + ac4) << 2),
                 WT + (size_t)(ncol0 + r) * K + k0 + ac4, true);
        }
    };

    load_stage(0, 0);
    asm volatile("cp.async.commit_group;" ::: "memory");
    load_stage(1, 1);
    asm volatile("cp.async.commit_group;" ::: "memory");

    #pragma unroll 1
    for (int kt = 0; kt < NIT; kt++) {
        asm volatile("cp.async.wait_group 1;" ::: "memory");
        __syncthreads();
        if (kt + 2 < NIT) load_stage(kt + 2, (kt + 2) % ST);
        asm volatile("cp.async.commit_group;" ::: "memory");

        const int buf = kt % ST;
        const uint32_t af_base = a_frag0 + (uint32_t)(buf * TILE_B);
        const uint32_t bf_base = b_frag0 + (uint32_t)(buf * TILE_B);

        #pragma unroll
        for (int ks = 0; ks < 4; ks++) {
            uint32_t af[2][4];
            #pragma unroll
            for (int i = 0; i < 2; i++) {
                ldsm4(af[i][0], af[i][1], af[i][2], af[i][3],
                      af_base + (uint32_t)(i * 16 * LDT * 4 + ks * 32));
                if (CVT_A) {
                    af[i][0] = cvt_u(af[i][0]); af[i][1] = cvt_u(af[i][1]);
                    af[i][2] = cvt_u(af[i][2]); af[i][3] = cvt_u(af[i][3]);
                }
            }
            uint32_t bf[2][4];
            ldsm4(bf[0][0], bf[0][1], bf[0][2], bf[0][3],
                  bf_base + (uint32_t)(ks * 32));
            ldsm4(bf[1][0], bf[1][1], bf[1][2], bf[1][3],
                  bf_base + (uint32_t)(16 * LDT * 4 + ks * 32));
            #pragma unroll
            for (int i = 0; i < 2; i++) {
                mma_tf32(d[i][0][0], d[i][0][1], d[i][0][2], d[i][0][3],
                         af[i][0], af[i][1], af[i][2], af[i][3], bf[0][0], bf[0][1]);
                mma_tf32(d[i][1][0], d[i][1][1], d[i][1][2], d[i][1][3],
                         af[i][0], af[i][1], af[i][2], af[i][3], bf[0][2], bf[0][3]);
                mma_tf32(d[i][2][0], d[i][2][1], d[i][2][2], d[i][2][3],
                         af[i][0], af[i][1], af[i][2], af[i][3], bf[1][0], bf[1][1]);
                mma_tf32(d[i][3][0], d[i][3][1], d[i][3][2], d[i][3][3],
                         af[i][0], af[i][1], af[i][2], af[i][3], bf[1][2], bf[1][3]);
            }
        }
    }

    #pragma unroll
    for (int j = 0; j < 4; j++) {
        float2 b = *reinterpret_cast<const float2*>(bias + ncol0 + wn * 32 + j * 8 + 2 * lr);
        #pragma unroll
        for (int i = 0; i < 2; i++) {
            d[i][j][0] += b.x; d[i][j][1] += b.y;
            d[i][j][2] += b.x; d[i][j][3] += b.y;
        }
    }

    const int cbase = ncol0 + wn * 32;
    #pragma unroll
    for (int i = 0; i < 2; i++) {
        #pragma unroll
        for (int rr = 0; rr < 2; rr++) {
            int gr = row0 + wm * 32 + i * 16 + lq + rr * 8;
            if (gr < M) {
                #pragma unroll
                for (int j = 0; j < 4; j++) {
                    float2 v;
                    if (EPI == 0) {
                        v.x = to_tf32(gelu_f(d[i][j][rr * 2 + 0]));
                        v.y = to_tf32(gelu_f(d[i][j][rr * 2 + 1]));
                    } else {
                        v.x = d[i][j][rr * 2 + 0];
                        v.y = d[i][j][rr * 2 + 1];
                    }
                    *reinterpret_cast<float2*>(
                        C + (size_t)gr * HDIM + cbase + j * 8 + 2 * lr) = v;
                }
            }
        }
    }
}

// ---------------------------------------------------------------------------
// kernel_launch
// ---------------------------------------------------------------------------
extern "C" void kernel_launch(void* const* d_in, const int* in_sizes, int n_in,
                              void* d_out, int out_size)
{
    const float* x_user    = (const float*)d_in[0];
    const float* x_item    = (const float*)d_in[1];
    const int*   ei_ui_src = (const int*)  d_in[2];
    const int*   ei_ui_dst = (const int*)  d_in[3];
    const int*   ei_iu_src = (const int*)  d_in[4];
    const int*   ei_iu_dst = (const int*)  d_in[5];
    const float* lin_user_W = (const float*)d_in[6];
    const float* lin_user_b = (const float*)d_in[7];
    const float* lin_item_W = (const float*)d_in[8];
    const float* lin_item_b = (const float*)d_in[9];
    const float* c0_ui_Wl = (const float*)d_in[10];
    const float* c0_ui_bl = (const float*)d_in[11];
    const float* c0_ui_Wr = (const float*)d_in[12];
    const float* c0_iu_Wl = (const float*)d_in[13];
    const float* c0_iu_bl = (const float*)d_in[14];
    const float* c0_iu_Wr = (const float*)d_in[15];
    const float* c1_ui_Wl = (const float*)d_in[16];
    const float* c1_ui_bl = (const float*)d_in[17];
    const float* c1_ui_Wr = (const float*)d_in[18];
    const float* c1_iu_Wl = (const float*)d_in[19];
    const float* c1_iu_bl = (const float*)d_in[20];
    const float* c1_iu_Wr = (const float*)d_in[21];
    const float* out_user_W = (const float*)d_in[22];
    const float* out_user_b = (const float*)d_in[23];
    const float* out_item_W = (const float*)d_in[24];
    const float* out_item_b = (const float*)d_in[25];
    const float* ln_user_g  = (const float*)d_in[26];
    const float* ln_user_b2 = (const float*)d_in[27];
    const float* ln_item_g  = (const float*)d_in[28];
    const float* ln_item_b2 = (const float*)d_in[29];

    float* out = (float*)d_out;
    const int nE = in_sizes[2];
    const int M  = NNODE;

    float *hu, *hi, *tu, *ti, *agg, *wts;
    int *deg, *off, *cur, *csr, *bsum, *bpre;
    cudaGetSymbolAddress((void**)&hu,  g_hu);
    cudaGetSymbolAddress((void**)&hi,  g_hi);
    cudaGetSymbolAddress((void**)&tu,  g_tu);
    cudaGetSymbolAddress((void**)&ti,  g_ti);
    cudaGetSymbolAddress((void**)&agg, g_agg);
    cudaGetSymbolAddress((void**)&deg, g_deg);
    cudaGetSymbolAddress((void**)&off, g_off);
    cudaGetSymbolAddress((void**)&cur, g_cur);
    cudaGetSymbolAddress((void**)&csr, g_csr);
    cudaGetSymbolAddress((void**)&bsum, g_bsum);
    cudaGetSymbolAddress((void**)&bpre, g_bpre);
    cudaGetSymbolAddress((void**)&wts, g_wts);

    float* agg0 = agg;
    float* agg1 = agg + (size_t)M * HDIM;
    int *deg0 = deg,     *deg1 = deg + M;
    int *off0 = off,     *off1 = off + M;
    int *cur0 = cur,     *cur1 = cur + M;
    int *csr0 = csr,     *csr1 = csr + EDGES;

    float* w_lin_u = wts;
    float* w_lin_i = w_lin_u + 32768;
    float* w_c[8];
    w_c[0] = w_lin_i + 32768;
    for (int i = 1; i < 8; i++) w_c[i] = w_c[i - 1] + 65536;
    float* w_out_u = w_c[7] + 65536;
    float* w_out_i = w_out_u + 65536;

    TPack tp;
    const float* twsrc[NTW] = {
        lin_user_W, lin_item_W,
        c0_ui_Wl, c0_ui_Wr, c0_iu_Wl, c0_iu_Wr,
        c1_ui_Wl, c1_ui_Wr, c1_iu_Wl, c1_iu_Wr,
        out_user_W, out_item_W };
    float* twdst[NTW] = {
        w_lin_u, w_lin_i,
        w_c[0], w_c[1], w_c[2], w_c[3], w_c[4], w_c[5], w_c[6], w_c[7],
        w_out_u, w_out_i };
    int twK[NTW] = { DIN, DIN, HDIM, HDIM, HDIM, HDIM, HDIM, HDIM, HDIM, HDIM, HDIM, HDIM };
    for (int i = 0; i < NTW; i++) { tp.src[i] = twsrc[i]; tp.dst[i] = twdst[i]; tp.K[i] = twK[i]; }

    EdgePair ep;
    ep.src[0] = ei_ui_src; ep.src[1] = ei_iu_src;
    ep.dst[0] = ei_ui_dst; ep.dst[1] = ei_iu_dst;
    ep.deg[0] = deg0; ep.deg[1] = deg1;
    ep.off[0] = off0; ep.off[1] = off1;
    ep.cur[0] = cur0; ep.cur[1] = cur1;
    ep.csr[0] = csr0; ep.csr[1] = csr1;

    dim3 blk(256);
    dim3 blkg(512);
    dim3 grid_gemm(2, (M + BM - 1) / BM, 2);
    dim3 grid_edge((nE + 255) / 256, 2);
    dim3 grid_scan(NB, 2);
    dim3 grid_agg((M + 7) / 8, 2, 2);
    dim3 grid_ln((M + 7) / 8, 2);
    dim3 grid_pro(640, NTW + 2);   // 64 blocks used per weight; 640 per deg side

    auto agg_pair = [&](const float* h0, const float* h1) {
        AggPair ap;
        ap.h[0] = h0;   ap.h[1] = h1;
        ap.csr[0] = csr0; ap.csr[1] = csr1;
        ap.off[0] = off0; ap.off[1] = off1;
        ap.deg[0] = deg0; ap.deg[1] = deg1;
        ap.agg[0] = agg0; ap.agg[1] = agg1;
        agg_pair_kernel<<<grid_agg, blk>>>(ap, M);
    };
    auto sage_pair = [&](const float* a1_0, const float* a2_0, float* wl0, float* wr0,
                         const float* bl0, float* c_0,
                         const float* a1_1, const float* a2_1, float* wl1, float* wr1,
                         const float* bl1, float* c_1) {
        GemmPair gp;
        gp.A1[0] = a1_0; gp.A2[0] = a2_0; gp.W1[0] = wl0; gp.W2[0] = wr0;
        gp.bias[0] = bl0; gp.C[0] = c_0;
        gp.A1[1] = a1_1; gp.A2[1] = a2_1; gp.W1[1] = wl1; gp.W2[1] = wr1;
        gp.bias[1] = bl1; gp.C[1] = c_1;
        gemm_pair<HDIM, true, 0, false><<<grid_gemm, blkg>>>(gp, M);
    };

    /* memset */ cudaMemsetAsync(deg, 0, 2 * M * sizeof(int));
    /* k1 */ prologue_kernel<<<grid_pro, blk>>>(tp, ep, nE);
    /* k2 */ bsum_pair_kernel<<<grid_scan, blk>>>(ep, M, bsum);
    /* k3 */ bscan_kernel<<<1, 32>>>(bsum, bpre);

    /* k4: input projections (pair, CVT_A) — PROFILED SLOT */
    {
        GemmPair gp;
        gp.A1[0] = x_user; gp.A2[0] = nullptr; gp.W1[0] = w_lin_u; gp.W2[0] = nullptr;
        gp.bias[0] = lin_user_b; gp.C[0] = hu;
        gp.A1[1] = x_item; gp.A2[1] = nullptr; gp.W1[1] = w_lin_i; gp.W2[1] = nullptr;
        gp.bias[1] = lin_item_b; gp.C[1] = hi;
        gemm_pair<DIN, false, 0, true><<<grid_gemm, blkg>>>(gp, M);
    }

    /* k5 */ addoff_pair_kernel<<<dim3(NB, 2), 1024>>>(ep, M, bpre);
    /* k6 */ csr_pair_kernel<<<grid_edge, blk>>>(ep, nE);

    /* k7: layer-0 aggregation (pair) */
    agg_pair(hu, hi);
    /* k8: layer-0 SAGE gemms (pair): ti, tu */
    sage_pair(agg0, hi, w_c[0], w_c[1], c0_ui_bl, ti,
              agg1, hu, w_c[2], w_c[3], c0_iu_bl, tu);

    /* k9: layer-1 aggregation (pair) */
    agg_pair(tu, ti);
    /* k10: layer-1 SAGE gemms (pair): hi, hu */
    sage_pair(agg0, ti, w_c[4], w_c[5], c1_ui_bl, hi,
              agg1, tu, w_c[6], w_c[7], c1_iu_bl, hu);

    /* k11: heads (pair) */
    {
        GemmPair gp;
        gp.A1[0] = hu; gp.A2[0] = nullptr; gp.W1[0] = w_out_u; gp.W2[0] = nullptr;
        gp.bias[0] = out_user_b; gp.C[0] = out;
        gp.A1[1] = hi; gp.A2[1] = nullptr; gp.W1[1] = w_out_i; gp.W2[1] = nullptr;
        gp.bias[1] = out_item_b; gp.C[1] = out + (size_t)M * HDIM;
        gemm_pair<HDIM, false, 1, false><<<grid_gemm, blkg>>>(gp, M);
    }
    /* k12: LayerNorm (pair) */
    {
        LnPair lp;
        lp.x[0] = out;                     lp.x[1] = out + (size_t)M * HDIM;
        lp.g[0] = ln_user_g;               lp.g[1] = ln_item_g;
        lp.b[0] = ln_user_b2;              lp.b[1] = ln_item_b2;
        ln_pair_kernel<<<grid_ln, blk>>>(lp, M);
    }
}

// round 15
// speedup vs baseline: 1.0282x; 1.0282x over previous
#include <cuda_runtime.h>
#include <math.h>
#include <stdint.h>

#define NNODE 100000
#define EDGES 800000
#define DIN   128
#define HDIM  256
#define NB    98          // scan blocks per side: ceil(100000/1024)

// ---------------------------------------------------------------------------
// Scratch (__device__ globals; no allocation allowed)
// ---------------------------------------------------------------------------
__device__ float g_hu [(size_t)NNODE * HDIM];
__device__ float g_hi [(size_t)NNODE * HDIM];
__device__ float g_tu [(size_t)NNODE * HDIM];
__device__ float g_ti [(size_t)NNODE * HDIM];
__device__ float g_agg[2 * (size_t)NNODE * HDIM];   // agg0 | agg1
__device__ int   g_deg[2 * NNODE];
__device__ int   g_off[2 * NNODE];
__device__ int   g_cur[2 * NNODE];
__device__ int   g_csr[2 * EDGES];
__device__ int   g_bsum[2 * NB];
__device__ int   g_bpre[2 * NB];
__device__ float g_wts[2 * 32768 + 10 * 65536];     // tf32 TRANSPOSED weights

// ---------------------------------------------------------------------------
// Helpers
// ---------------------------------------------------------------------------
__device__ __forceinline__ float gelu_f(float x) {
    return 0.5f * x * (1.0f + erff(x * 0.70710678118654752f));
}
__device__ __forceinline__ float to_tf32(float x) {
    float r;
    asm("cvt.rna.tf32.f32 %0, %1;" : "=f"(r) : "f"(x));
    return r;
}
__device__ __forceinline__ uint32_t cvt_u(uint32_t x) {
    return __float_as_uint(to_tf32(__uint_as_float(x)));
}
__device__ __forceinline__ void mma_tf32(float& d0, float& d1, float& d2, float& d3,
                                         uint32_t a0, uint32_t a1, uint32_t a2, uint32_t a3,
                                         uint32_t b0, uint32_t b1)
{
    asm volatile(
        "mma.sync.aligned.m16n8k8.row.col.f32.tf32.tf32.f32 "
        "{%0,%1,%2,%3}, {%4,%5,%6,%7}, {%8,%9}, {%0,%1,%2,%3};"
        : "+f"(d0), "+f"(d1), "+f"(d2), "+f"(d3)
        : "r"(a0), "r"(a1), "r"(a2), "r"(a3), "r"(b0), "r"(b1));
}
__device__ __forceinline__ void cp16(uint32_t dst, const void* src, bool pred) {
    int sz = pred ? 16 : 0;
    asm volatile("cp.async.ca.shared.global [%0], [%1], 16, %2;"
                 :: "r"(dst), "l"(src), "r"(sz));
}
__device__ __forceinline__ void ldsm4(uint32_t& r0, uint32_t& r1, uint32_t& r2, uint32_t& r3,
                                      uint32_t addr)
{
    asm volatile("ldmatrix.sync.aligned.m8n8.x4.shared.b16 {%0,%1,%2,%3}, [%4];"
                 : "=r"(r0), "=r"(r1), "=r"(r2), "=r"(r3) : "r"(addr));
}

// ---------------------------------------------------------------------------
// CSR structs
// ---------------------------------------------------------------------------
struct EdgePair {
    const int* src[2];
    const int* dst[2];
    int*       deg[2];
    int*       off[2];
    int*       cur[2];
    int*       csr[2];
};

// ---------------------------------------------------------------------------
// Merged prologue: weight transpose-convert (y < NTW) + degree count (y >= NTW)
// ---------------------------------------------------------------------------
#define NTW 12
struct TPack { const float* src[NTW]; float* dst[NTW]; int K[NTW]; };

__global__ void __launch_bounds__(256)
prologue_kernel(TPack p, EdgePair ep, int nE)
{
    int m = blockIdx.y;
    if (m < NTW) {
        int K = p.K[m];
        int kt = (blockIdx.x & 7) * 32;
        int nt = (blockIdx.x >> 3) * 32;
        if (blockIdx.x >= 64 || kt >= K) return;
        __shared__ float tile[32][33];
        const float* __restrict__ s = p.src[m];
        float*       __restrict__ d = p.dst[m];
        int tx = threadIdx.x & 31;
        int ty = threadIdx.x >> 5;
        #pragma unroll
        for (int u = 0; u < 4; u++) {
            int r = ty + u * 8;
            tile[r][tx] = to_tf32(s[(size_t)(kt + r) * 256 + nt + tx]);
        }
        __syncthreads();
        #pragma unroll
        for (int u = 0; u < 4; u++) {
            int r = ty + u * 8;
            d[(size_t)(nt + r) * K + kt + tx] = tile[tx][r];
        }
    } else {
        int z = m - NTW;
        const int* __restrict__ dst = ep.dst[z];
        int* __restrict__ deg = ep.deg[z];
        for (int i = blockIdx.x * blockDim.x + threadIdx.x; i < nE;
             i += gridDim.x * blockDim.x)
            atomicAdd(&deg[dst[i]], 1);
    }
}

// ---------------------------------------------------------------------------
// Multi-block scan
// ---------------------------------------------------------------------------
__global__ void __launch_bounds__(256)
bsum_pair_kernel(EdgePair p, int n, int* __restrict__ bsum)
{
    int z = blockIdx.y;
    int b = blockIdx.x;
    int t = threadIdx.x;
    int base = b * 1024;
    int s = 0;
    #pragma unroll
    for (int u = 0; u < 4; u++) {
        int i = base + t + u * 256;
        if (i < n) s += p.deg[z][i];
    }
    #pragma unroll
    for (int m = 16; m > 0; m >>= 1) s += __shfl_xor_sync(0xffffffffu, s, m);
    __shared__ int ws[8];
    if ((t & 31) == 0) ws[t >> 5] = s;
    __syncthreads();
    if (t < 8) {
        int v = ws[t];
        #pragma unroll
        for (int m = 4; m > 0; m >>= 1) v += __shfl_xor_sync(0xffu, v, m);
        if (t == 0) bsum[z * NB + b] = v;
    }
}

__global__ void __launch_bounds__(32)
bscan_kernel(const int* __restrict__ bsum, int* __restrict__ bpre)
{
    int z = threadIdx.x;
    if (z < 2) {
        int acc = 0;
        for (int b = 0; b < NB; b++) {
            bpre[z * NB + b] = acc;
            acc += bsum[z * NB + b];
        }
    }
}

__global__ void __launch_bounds__(1024)
addoff_pair_kernel(EdgePair p, int n, const int* __restrict__ bpre)
{
    int z = blockIdx.y;
    int b = blockIdx.x;
    int i = b * 1024 + threadIdx.x;
    int lane = threadIdx.x & 31;
    int wid  = threadIdx.x >> 5;
    int v = (i < n) ? p.deg[z][i] : 0;
    int x = v;
    #pragma unroll
    for (int s = 1; s < 32; s <<= 1) {
        int y = __shfl_up_sync(0xffffffffu, x, s);
        if (lane >= s) x += y;
    }
    __shared__ int ws[32];
    if (lane == 31) ws[wid] = x;
    __syncthreads();
    if (wid == 0) {
        int w = ws[lane];
        #pragma unroll
        for (int s = 1; s < 32; s <<= 1) {
            int y = __shfl_up_sync(0xffffffffu, w, s);
            if (lane >= s) w += y;
        }
        ws[lane] = w;
    }
    __syncthreads();
    int excl = x - v + (wid > 0 ? ws[wid - 1] : 0) + bpre[z * NB + b];
    if (i < n) { p.off[z][i] = excl; p.cur[z][i] = excl; }
}

__global__ void __launch_bounds__(256)
csr_pair_kernel(EdgePair p, int nE)
{
    int z = blockIdx.y;
    int e = blockIdx.x * blockDim.x + threadIdx.x;
    if (e >= nE) return;
    int pos = atomicAdd(&p.cur[z][p.dst[z][e]], 1);
    p.csr[z][pos] = p.src[z][e];
}

// ---------------------------------------------------------------------------
// Paired CSR aggregation
// ---------------------------------------------------------------------------
struct AggPair {
    const float* h[2];
    const int*   csr[2];
    const int*   off[2];
    const int*   deg[2];
    float*       agg[2];
};

__global__ void __launch_bounds__(256)
agg_pair_kernel(AggPair p, int n)
{
    int node = blockIdx.x * 8 + (threadIdx.x >> 5);
    if (node >= n) return;
    const int z = blockIdx.z;
    const float* __restrict__ h   = p.h[z];
    const int*   __restrict__ csr = p.csr[z];
    float*       __restrict__ agg = p.agg[z];
    int coff = blockIdx.y * 128;
    int lane = threadIdx.x & 31;
    int o = __ldg(&p.off[z][node]);
    int d = __ldg(&p.deg[z][node]);
    float4 acc = make_float4(0.f, 0.f, 0.f, 0.f);
    int j = 0;
    for (; j + 4 <= d; j += 4) {
        int s0 = __ldg(&csr[o + j]);
        int s1 = __ldg(&csr[o + j + 1]);
        int s2 = __ldg(&csr[o + j + 2]);
        int s3 = __ldg(&csr[o + j + 3]);
        float4 v0 = *reinterpret_cast<const float4*>(h + (size_t)s0 * HDIM + coff + lane * 4);
        float4 v1 = *reinterpret_cast<const float4*>(h + (size_t)s1 * HDIM + coff + lane * 4);
        float4 v2 = *reinterpret_cast<const float4*>(h + (size_t)s2 * HDIM + coff + lane * 4);
        float4 v3 = *reinterpret_cast<const float4*>(h + (size_t)s3 * HDIM + coff + lane * 4);
        acc.x += v0.x + v1.x + v2.x + v3.x;
        acc.y += v0.y + v1.y + v2.y + v3.y;
        acc.z += v0.z + v1.z + v2.z + v3.z;
        acc.w += v0.w + v1.w + v2.w + v3.w;
    }
    for (; j < d; j++) {
        int s = __ldg(&csr[o + j]);
        float4 v = *reinterpret_cast<const float4*>(h + (size_t)s * HDIM + coff + lane * 4);
        acc.x += v.x; acc.y += v.y; acc.z += v.z; acc.w += v.w;
    }
    float sc = 1.0f / fmaxf((float)d, 1.0f);
    float4 r;
    r.x = to_tf32(acc.x * sc);
    r.y = to_tf32(acc.y * sc);
    r.z = to_tf32(acc.z * sc);
    r.w = to_tf32(acc.w * sc);
    *reinterpret_cast<float4*>(agg + (size_t)node * HDIM + coff + lane * 4) = r;
}

// ---------------------------------------------------------------------------
// Paired in-place LayerNorm
// ---------------------------------------------------------------------------
struct LnPair {
    float*       x[2];
    const float* g[2];
    const float* b[2];
};

__global__ void __launch_bounds__(256)
ln_pair_kernel(LnPair pp, int M)
{
    int row  = blockIdx.x * 8 + (threadIdx.x >> 5);
    int lane = threadIdx.x & 31;
    if (row >= M) return;
    const int z = blockIdx.y;
    float* p = pp.x[z] + (size_t)row * HDIM + lane * 8;
    const float* g = pp.g[z];
    const float* b = pp.b[z];
    float4 v0 = *reinterpret_cast<const float4*>(p);
    float4 v1 = *reinterpret_cast<const float4*>(p + 4);
    float s  = v0.x + v0.y + v0.z + v0.w + v1.x + v1.y + v1.z + v1.w;
    float sq = v0.x*v0.x + v0.y*v0.y + v0.z*v0.z + v0.w*v0.w
             + v1.x*v1.x + v1.y*v1.y + v1.z*v1.z + v1.w*v1.w;
    #pragma unroll
    for (int m = 16; m > 0; m >>= 1) {
        s  += __shfl_xor_sync(0xffffffffu, s,  m);
        sq += __shfl_xor_sync(0xffffffffu, sq, m);
    }
    float mu   = s * (1.0f / 256.0f);
    float var  = sq * (1.0f / 256.0f) - mu * mu;
    float rstd = rsqrtf(var + 1e-5f);
    float4 g0 = *reinterpret_cast<const float4*>(g + lane * 8);
    float4 g1 = *reinterpret_cast<const float4*>(g + lane * 8 + 4);
    float4 b0 = *reinterpret_cast<const float4*>(b + lane * 8);
    float4 b1 = *reinterpret_cast<const float4*>(b + lane * 8 + 4);
    float4 o0, o1;
    o0.x = (v0.x - mu) * rstd * g0.x + b0.x;
    o0.y = (v0.y - mu) * rstd * g0.y + b0.y;
    o0.z = (v0.z - mu) * rstd * g0.z + b0.z;
    o0.w = (v0.w - mu) * rstd * g0.w + b0.w;
    o1.x = (v1.x - mu) * rstd * g1.x + b1.x;
    o1.y = (v1.y - mu) * rstd * g1.y + b1.y;
    o1.z = (v1.z - mu) * rstd * g1.z + b1.z;
    o1.w = (v1.w - mu) * rstd * g1.w + b1.w;
    *reinterpret_cast<float4*>(p)     = o0;
    *reinterpret_cast<float4*>(p + 4) = o1;
}

// ---------------------------------------------------------------------------
// Paired 3-stage cp.async tf32 GEMM — R13 shape (256 thr, 8 warps, 64x32 tile)
// + CVT_A option (raw fp32 A, fragments converted post-ldmatrix).
// Grid: (ncol=2 fast, rowblk, side=2) for L2 A-reuse.
// ---------------------------------------------------------------------------
constexpr int BM   = 128;
constexpr int BK   = 32;
constexpr int LDT  = 36;
constexpr int TILE_B = BM * LDT * 4;
constexpr int ST   = 3;

struct GemmPair {
    const float* A1[2];
    const float* A2[2];
    const float* W1[2];   // transposed [256][K], tf32
    const float* W2[2];
    const float* bias[2];
    float*       C[2];
};

template<int K, bool HAS_A2, int EPI, bool CVT_A>
__global__ void __launch_bounds__(256, 2)
gemm_pair(GemmPair p, int M)
{
    __shared__ float a_s[ST][BM * LDT];
    __shared__ float b_s[ST][BM * LDT];

    constexpr int NIT = (HAS_A2 ? 2 : 1) * K / BK;

    const int zz = blockIdx.z;
    const float* __restrict__ A1g  = p.A1[zz];
    const float* __restrict__ A2g  = p.A2[zz];
    const float* __restrict__ W1g  = p.W1[zz];
    const float* __restrict__ W2g  = p.W2[zz];
    const float* __restrict__ bias = p.bias[zz];
    float*       __restrict__ C    = p.C[zz];

    const int tid  = threadIdx.x;
    const int lane = tid & 31;
    const int wid  = tid >> 5;
    const int wm   = wid >> 2;
    const int wn   = wid & 3;
    const int lq   = lane >> 2;
    const int lr   = lane & 3;
    const int row0 = blockIdx.y * BM;
    const int ncol0 = blockIdx.x * 128;

    const int ar  = tid >> 3;
    const int ac4 = (tid & 7) << 2;

    const uint32_t a_base = (uint32_t)__cvta_generic_to_shared(a_s);
    const uint32_t b_base = (uint32_t)__cvta_generic_to_shared(b_s);

    const int g8 = lane >> 3;
    const int l8 = lane & 7;
    const int row_a = ((g8 & 1) << 3) + l8;
    const int col_a = (g8 >> 1) << 2;
    const uint32_t a_frag0 = a_base + (uint32_t)(((wm * 64 + row_a) * LDT + col_a) << 2);
    const int row_b = ((g8 >> 1) << 3) + l8;
    const int col_b = (g8 & 1) << 2;
    const uint32_t b_frag0 = b_base + (uint32_t)(((wn * 32 + row_b) * LDT + col_b) << 2);

    float d[4][4][4];
    #pragma unroll
    for (int i = 0; i < 4; i++)
        #pragma unroll
        for (int j = 0; j < 4; j++)
            #pragma unroll
            for (int q = 0; q < 4; q++)
                d[i][j][q] = 0.f;

    auto load_stage = [&](int kt, int buf) {
        int kk = kt * BK;
        const float* __restrict__ A  = (HAS_A2 && kk >= K) ? A2g : A1g;
        const float* __restrict__ WT = (HAS_A2 && kk >= K) ? W2g : W1g;
        const int k0 = HAS_A2 ? (kk & (K - 1)) : kk;
        uint32_t ab = a_base + (uint32_t)(buf * TILE_B);
        uint32_t bb = b_base + (uint32_t)(buf * TILE_B);
        #pragma unroll
        for (int u = 0; u < 4; u++) {
            int r  = ar + u * 32;
            int gr = row0 + r;
            int gc = gr < M ? gr : (M - 1);
            cp16(ab + (uint32_t)((r * LDT + ac4) << 2),
                 A + (size_t)gc * K + k0 + ac4, gr < M);
            cp16(bb + (uint32_t)((r * LDT + ac4) << 2),
                 WT + (size_t)(ncol0 + r) * K + k0 + ac4, true);
        }
    };

    load_stage(0, 0);
    asm volatile("cp.async.commit_group;" ::: "memory");
    load_stage(1, 1);
    asm volatile("cp.async.commit_group;" ::: "memory");

    #pragma unroll 1
    for (int kt = 0; kt < NIT; kt++) {
        asm volatile("cp.async.wait_group 1;" ::: "memory");
        __syncthreads();
        if (kt + 2 < NIT) load_stage(kt + 2, (kt + 2) % ST);
        asm volatile("cp.async.commit_group;" ::: "memory");

        const int buf = kt % ST;
        const uint32_t af_base = a_frag0 + (uint32_t)(buf * TILE_B);
        const uint32_t bf_base = b_frag0 + (uint32_t)(buf * TILE_B);

        #pragma unroll
        for (int ks = 0; ks < 4; ks++) {
            uint32_t af[4][4];
            #pragma unroll
            for (int i = 0; i < 4; i++) {
                ldsm4(af[i][0], af[i][1], af[i][2], af[i][3],
                      af_base + (uint32_t)(i * 16 * LDT * 4 + ks * 32));
                if (CVT_A) {
                    af[i][0] = cvt_u(af[i][0]); af[i][1] = cvt_u(af[i][1]);
                    af[i][2] = cvt_u(af[i][2]); af[i][3] = cvt_u(af[i][3]);
                }
            }
            uint32_t bf[2][4];
            ldsm4(bf[0][0], bf[0][1], bf[0][2], bf[0][3],
                  bf_base + (uint32_t)(ks * 32));
            ldsm4(bf[1][0], bf[1][1], bf[1][2], bf[1][3],
                  bf_base + (uint32_t)(16 * LDT * 4 + ks * 32));
            #pragma unroll
            for (int i = 0; i < 4; i++) {
                mma_tf32(d[i][0][0], d[i][0][1], d[i][0][2], d[i][0][3],
                         af[i][0], af[i][1], af[i][2], af[i][3], bf[0][0], bf[0][1]);
                mma_tf32(d[i][1][0], d[i][1][1], d[i][1][2], d[i][1][3],
                         af[i][0], af[i][1], af[i][2], af[i][3], bf[0][2], bf[0][3]);
                mma_tf32(d[i][2][0], d[i][2][1], d[i][2][2], d[i][2][3],
                         af[i][0], af[i][1], af[i][2], af[i][3], bf[1][0], bf[1][1]);
                mma_tf32(d[i][3][0], d[i][3][1], d[i][3][2], d[i][3][3],
                         af[i][0], af[i][1], af[i][2], af[i][3], bf[1][2], bf[1][3]);
            }
        }
    }

    #pragma unroll
    for (int j = 0; j < 4; j++) {
        float2 b = *reinterpret_cast<const float2*>(bias + ncol0 + wn * 32 + j * 8 + 2 * lr);
        #pragma unroll
        for (int i = 0; i < 4; i++) {
            d[i][j][0] += b.x; d[i][j][1] += b.y;
            d[i][j][2] += b.x; d[i][j][3] += b.y;
        }
    }

    const int cbase = ncol0 + wn * 32;
    #pragma unroll
    for (int i = 0; i < 4; i++) {
        #pragma unroll
        for (int rr = 0; rr < 2; rr++) {
            int gr = row0 + wm * 64 + i * 16 + lq + rr * 8;
            if (gr < M) {
                #pragma unroll
                for (int j = 0; j < 4; j++) {
                    float2 v;
                    if (EPI == 0) {
                        v.x = to_tf32(gelu_f(d[i][j][rr * 2 + 0]));
                        v.y = to_tf32(gelu_f(d[i][j][rr * 2 + 1]));
                    } else {
                        v.x = d[i][j][rr * 2 + 0];
                        v.y = d[i][j][rr * 2 + 1];
                    }
                    *reinterpret_cast<float2*>(
                        C + (size_t)gr * HDIM + cbase + j * 8 + 2 * lr) = v;
                }
            }
        }
    }
}

// ---------------------------------------------------------------------------
// kernel_launch
// ---------------------------------------------------------------------------
extern "C" void kernel_launch(void* const* d_in, const int* in_sizes, int n_in,
                              void* d_out, int out_size)
{
    const float* x_user    = (const float*)d_in[0];
    const float* x_item    = (const float*)d_in[1];
    const int*   ei_ui_src = (const int*)  d_in[2];
    const int*   ei_ui_dst = (const int*)  d_in[3];
    const int*   ei_iu_src = (const int*)  d_in[4];
    const int*   ei_iu_dst = (const int*)  d_in[5];
    const float* lin_user_W = (const float*)d_in[6];
    const float* lin_user_b = (const float*)d_in[7];
    const float* lin_item_W = (const float*)d_in[8];
    const float* lin_item_b = (const float*)d_in[9];
    const float* c0_ui_Wl = (const float*)d_in[10];
    const float* c0_ui_bl = (const float*)d_in[11];
    const float* c0_ui_Wr = (const float*)d_in[12];
    const float* c0_iu_Wl = (const float*)d_in[13];
    const float* c0_iu_bl = (const float*)d_in[14];
    const float* c0_iu_Wr = (const float*)d_in[15];
    const float* c1_ui_Wl = (const float*)d_in[16];
    const float* c1_ui_bl = (const float*)d_in[17];
    const float* c1_ui_Wr = (const float*)d_in[18];
    const float* c1_iu_Wl = (const float*)d_in[19];
    const float* c1_iu_bl = (const float*)d_in[20];
    const float* c1_iu_Wr = (const float*)d_in[21];
    const float* out_user_W = (const float*)d_in[22];
    const float* out_user_b = (const float*)d_in[23];
    const float* out_item_W = (const float*)d_in[24];
    const float* out_item_b = (const float*)d_in[25];
    const float* ln_user_g  = (const float*)d_in[26];
    const float* ln_user_b2 = (const float*)d_in[27];
    const float* ln_item_g  = (const float*)d_in[28];
    const float* ln_item_b2 = (const float*)d_in[29];

    float* out = (float*)d_out;
    const int nE = in_sizes[2];
    const int M  = NNODE;

    float *hu, *hi, *tu, *ti, *agg, *wts;
    int *deg, *off, *cur, *csr, *bsum, *bpre;
    cudaGetSymbolAddress((void**)&hu,  g_hu);
    cudaGetSymbolAddress((void**)&hi,  g_hi);
    cudaGetSymbolAddress((void**)&tu,  g_tu);
    cudaGetSymbolAddress((void**)&ti,  g_ti);
    cudaGetSymbolAddress((void**)&agg, g_agg);
    cudaGetSymbolAddress((void**)&deg, g_deg);
    cudaGetSymbolAddress((void**)&off, g_off);
    cudaGetSymbolAddress((void**)&cur, g_cur);
    cudaGetSymbolAddress((void**)&csr, g_csr);
    cudaGetSymbolAddress((void**)&bsum, g_bsum);
    cudaGetSymbolAddress((void**)&bpre, g_bpre);
    cudaGetSymbolAddress((void**)&wts, g_wts);

    float* agg0 = agg;
    float* agg1 = agg + (size_t)M * HDIM;
    int *deg0 = deg,     *deg1 = deg + M;
    int *off0 = off,     *off1 = off + M;
    int *cur0 = cur,     *cur1 = cur + M;
    int *csr0 = csr,     *csr1 = csr + EDGES;

    float* w_lin_u = wts;
    float* w_lin_i = w_lin_u + 32768;
    float* w_c[8];
    w_c[0] = w_lin_i + 32768;
    for (int i = 1; i < 8; i++) w_c[i] = w_c[i - 1] + 65536;
    float* w_out_u = w_c[7] + 65536;
    float* w_out_i = w_out_u + 65536;

    TPack tp;
    const float* twsrc[NTW] = {
        lin_user_W, lin_item_W,
        c0_ui_Wl, c0_ui_Wr, c0_iu_Wl, c0_iu_Wr,
        c1_ui_Wl, c1_ui_Wr, c1_iu_Wl, c1_iu_Wr,
        out_user_W, out_item_W };
    float* twdst[NTW] = {
        w_lin_u, w_lin_i,
        w_c[0], w_c[1], w_c[2], w_c[3], w_c[4], w_c[5], w_c[6], w_c[7],
        w_out_u, w_out_i };
    int twK[NTW] = { DIN, DIN, HDIM, HDIM, HDIM, HDIM, HDIM, HDIM, HDIM, HDIM, HDIM, HDIM };
    for (int i = 0; i < NTW; i++) { tp.src[i] = twsrc[i]; tp.dst[i] = twdst[i]; tp.K[i] = twK[i]; }

    EdgePair ep;
    ep.src[0] = ei_ui_src; ep.src[1] = ei_iu_src;
    ep.dst[0] = ei_ui_dst; ep.dst[1] = ei_iu_dst;
    ep.deg[0] = deg0; ep.deg[1] = deg1;
    ep.off[0] = off0; ep.off[1] = off1;
    ep.cur[0] = cur0; ep.cur[1] = cur1;
    ep.csr[0] = csr0; ep.csr[1] = csr1;

    dim3 blk(256);
    dim3 grid_gemm(2, (M + BM - 1) / BM, 2);
    dim3 grid_edge((nE + 255) / 256, 2);
    dim3 grid_scan(NB, 2);
    dim3 grid_agg((M + 7) / 8, 2, 2);
    dim3 grid_ln((M + 7) / 8, 2);
    dim3 grid_pro(640, NTW + 2);

    auto agg_pair = [&](const float* h0, const float* h1) {
        AggPair ap;
        ap.h[0] = h0;   ap.h[1] = h1;
        ap.csr[0] = csr0; ap.csr[1] = csr1;
        ap.off[0] = off0; ap.off[1] = off1;
        ap.deg[0] = deg0; ap.deg[1] = deg1;
        ap.agg[0] = agg0; ap.agg[1] = agg1;
        agg_pair_kernel<<<grid_agg, blk>>>(ap, M);
    };
    auto sage_pair = [&](const float* a1_0, const float* a2_0, float* wl0, float* wr0,
                         const float* bl0, float* c_0,
                         const float* a1_1, const float* a2_1, float* wl1, float* wr1,
                         const float* bl1, float* c_1) {
        GemmPair gp;
        gp.A1[0] = a1_0; gp.A2[0] = a2_0; gp.W1[0] = wl0; gp.W2[0] = wr0;
        gp.bias[0] = bl0; gp.C[0] = c_0;
        gp.A1[1] = a1_1; gp.A2[1] = a2_1; gp.W1[1] = wl1; gp.W2[1] = wr1;
        gp.bias[1] = bl1; gp.C[1] = c_1;
        gemm_pair<HDIM, true, 0, false><<<grid_gemm, blk>>>(gp, M);
    };

    /* memset */ cudaMemsetAsync(deg, 0, 2 * M * sizeof(int));
    /* k1 */ prologue_kernel<<<grid_pro, blk>>>(tp, ep, nE);
    /* k2 */ bsum_pair_kernel<<<grid_scan, blk>>>(ep, M, bsum);
    /* k3 */ bscan_kernel<<<1, 32>>>(bsum, bpre);

    /* k4: input projections (pair, CVT_A) — PROFILED SLOT */
    {
        GemmPair gp;
        gp.A1[0] = x_user; gp.A2[0] = nullptr; gp.W1[0] = w_lin_u; gp.W2[0] = nullptr;
        gp.bias[0] = lin_user_b; gp.C[0] = hu;
        gp.A1[1] = x_item; gp.A2[1] = nullptr; gp.W1[1] = w_lin_i; gp.W2[1] = nullptr;
        gp.bias[1] = lin_item_b; gp.C[1] = hi;
        gemm_pair<DIN, false, 0, true><<<grid_gemm, blk>>>(gp, M);
    }

    /* k5 */ addoff_pair_kernel<<<dim3(NB, 2), 1024>>>(ep, M, bpre);
    /* k6 */ csr_pair_kernel<<<grid_edge, blk>>>(ep, nE);

    /* k7: layer-0 aggregation (pair) */
    agg_pair(hu, hi);
    /* k8: layer-0 SAGE gemms (pair): ti, tu */
    sage_pair(agg0, hi, w_c[0], w_c[1], c0_ui_bl, ti,
              agg1, hu, w_c[2], w_c[3], c0_iu_bl, tu);

    /* k9: layer-1 aggregation (pair) */
    agg_pair(tu, ti);
    /* k10: layer-1 SAGE gemms (pair): hi, hu */
    sage_pair(agg0, ti, w_c[4], w_c[5], c1_ui_bl, hi,
              agg1, tu, w_c[6], w_c[7], c1_iu_bl, hu);

    /* k11: heads (pair) */
    {
        GemmPair gp;
        gp.A1[0] = hu; gp.A2[0] = nullptr; gp.W1[0] = w_out_u; gp.W2[0] = nullptr;
        gp.bias[0] = out_user_b; gp.C[0] = out;
        gp.A1[1] = hi; gp.A2[1] = nullptr; gp.W1[1] = w_out_i; gp.W2[1] = nullptr;
        gp.bias[1] = out_item_b; gp.C[1] = out + (size_t)M * HDIM;
        gemm_pair<HDIM, false, 1, false><<<grid_gemm, blk>>>(gp, M);
    }
    /* k12: LayerNorm (pair) */
    {
        LnPair lp;
        lp.x[0] = out;                     lp.x[1] = out + (size_t)M * HDIM;
        lp.g[0] = ln_user_g;               lp.g[1] = ln_item_g;
        lp.b[0] = ln_user_b2;              lp.b[1] = ln_item_b2;
        ln_pair_kernel<<<grid_ln, blk>>>(lp, M);
    }
}

// round 16
// speedup vs baseline: 1.6057x; 1.5617x over previous
#include <cuda_runtime.h>
#include <cuda_fp16.h>
#include <math.h>
#include <stdint.h>

#define NNODE 100000
#define EDGES 800000
#define DIN   128
#define HDIM  256
#define NB    98          // scan blocks per side

// ---------------------------------------------------------------------------
// Scratch (__device__ globals)
// ---------------------------------------------------------------------------
__device__ __half g_hu [(size_t)NNODE * HDIM];
__device__ __half g_hi [(size_t)NNODE * HDIM];
__device__ __half g_tu [(size_t)NNODE * HDIM];
__device__ __half g_ti [(size_t)NNODE * HDIM];
__device__ __half g_agg[2 * (size_t)NNODE * HDIM];
__device__ __half g_x16[2 * (size_t)NNODE * DIN];
__device__ __half g_wts[2 * 32768 + 10 * 65536];    // fp16 TRANSPOSED weights
__device__ int    g_deg[2 * NNODE];
__device__ int    g_off[2 * NNODE];
__device__ int    g_cur[2 * NNODE];
__device__ int    g_csr[2 * EDGES];
__device__ int    g_bsum[2 * NB];
__device__ int    g_bpre[2 * NB];

// ---------------------------------------------------------------------------
// Helpers
// ---------------------------------------------------------------------------
__device__ __forceinline__ float gelu_f(float x) {
    return 0.5f * x * (1.0f + erff(x * 0.70710678118654752f));
}
__device__ __forceinline__ void mma_f16(float& d0, float& d1, float& d2, float& d3,
                                        uint32_t a0, uint32_t a1, uint32_t a2, uint32_t a3,
                                        uint32_t b0, uint32_t b1)
{
    asm volatile(
        "mma.sync.aligned.m16n8k16.row.col.f32.f16.f16.f32 "
        "{%0,%1,%2,%3}, {%4,%5,%6,%7}, {%8,%9}, {%0,%1,%2,%3};"
        : "+f"(d0), "+f"(d1), "+f"(d2), "+f"(d3)
        : "r"(a0), "r"(a1), "r"(a2), "r"(a3), "r"(b0), "r"(b1));
}
__device__ __forceinline__ void cp16(uint32_t dst, const void* src, bool pred) {
    int sz = pred ? 16 : 0;
    asm volatile("cp.async.ca.shared.global [%0], [%1], 16, %2;"
                 :: "r"(dst), "l"(src), "r"(sz));
}
__device__ __forceinline__ void ldsm4(uint32_t& r0, uint32_t& r1, uint32_t& r2, uint32_t& r3,
                                      uint32_t addr)
{
    asm volatile("ldmatrix.sync.aligned.m8n8.x4.shared.b16 {%0,%1,%2,%3}, [%4];"
                 : "=r"(r0), "=r"(r1), "=r"(r2), "=r"(r3) : "r"(addr));
}

// ---------------------------------------------------------------------------
// CSR structs
// ---------------------------------------------------------------------------
struct EdgePair {
    const int* src[2];
    const int* dst[2];
    int*       deg[2];
    int*       off[2];
    int*       cur[2];
    int*       csr[2];
};

// ---------------------------------------------------------------------------
// Merged prologue:
//   y < NTW            : weight transpose-convert fp32 [K][256] -> fp16 [256][K]
//   y in [NTW, NTW+2)  : degree count
//   y in [NTW+2,NTW+4) : x fp32 -> fp16
// ---------------------------------------------------------------------------
#define NTW 12
struct TPack { const float* src[NTW]; __half* dst[NTW]; int K[NTW]; };
struct XPack { const float* src[2]; __half* dst[2]; };

__global__ void __launch_bounds__(256)
prologue_kernel(TPack p, XPack xp, EdgePair ep, int nE)
{
    int m = blockIdx.y;
    if (m < NTW) {
        int K = p.K[m];
        int kt = (blockIdx.x & 7) * 32;
        int nt = (blockIdx.x >> 3) * 32;
        if (blockIdx.x >= 64 || kt >= K) return;
        __shared__ float tile[32][33];
        const float* __restrict__ s = p.src[m];
        __half*      __restrict__ d = p.dst[m];
        int tx = threadIdx.x & 31;
        int ty = threadIdx.x >> 5;
        #pragma unroll
        for (int u = 0; u < 4; u++) {
            int r = ty + u * 8;
            tile[r][tx] = s[(size_t)(kt + r) * 256 + nt + tx];
        }
        __syncthreads();
        #pragma unroll
        for (int u = 0; u < 4; u++) {
            int r = ty + u * 8;
            d[(size_t)(nt + r) * K + kt + tx] = __float2half_rn(tile[tx][r]);
        }
    } else if (m < NTW + 2) {
        int z = m - NTW;
        const int* __restrict__ dst = ep.dst[z];
        int* __restrict__ deg = ep.deg[z];
        for (int i = blockIdx.x * blockDim.x + threadIdx.x; i < nE;
             i += gridDim.x * blockDim.x)
            atomicAdd(&deg[dst[i]], 1);
    } else {
        int z = m - NTW - 2;
        const float4* __restrict__ s = reinterpret_cast<const float4*>(xp.src[z]);
        __half* __restrict__ d = xp.dst[z];
        int n4 = NNODE * DIN / 4;
        for (int i = blockIdx.x * blockDim.x + threadIdx.x; i < n4;
             i += gridDim.x * blockDim.x) {
            float4 v = s[i];
            __half2* o = reinterpret_cast<__half2*>(d + i * 4);
            o[0] = __floats2half2_rn(v.x, v.y);
            o[1] = __floats2half2_rn(v.z, v.w);
        }
    }
}

// ---------------------------------------------------------------------------
// Multi-block scan
// ---------------------------------------------------------------------------
__global__ void __launch_bounds__(256)
bsum_pair_kernel(EdgePair p, int n, int* __restrict__ bsum)
{
    int z = blockIdx.y;
    int b = blockIdx.x;
    int t = threadIdx.x;
    int base = b * 1024;
    int s = 0;
    #pragma unroll
    for (int u = 0; u < 4; u++) {
        int i = base + t + u * 256;
        if (i < n) s += p.deg[z][i];
    }
    #pragma unroll
    for (int m = 16; m > 0; m >>= 1) s += __shfl_xor_sync(0xffffffffu, s, m);
    __shared__ int ws[8];
    if ((t & 31) == 0) ws[t >> 5] = s;
    __syncthreads();
    if (t < 8) {
        int v = ws[t];
        #pragma unroll
        for (int m = 4; m > 0; m >>= 1) v += __shfl_xor_sync(0xffu, v, m);
        if (t == 0) bsum[z * NB + b] = v;
    }
}

__global__ void __launch_bounds__(32)
bscan_kernel(const int* __restrict__ bsum, int* __restrict__ bpre)
{
    int z = threadIdx.x;
    if (z < 2) {
        int acc = 0;
        for (int b = 0; b < NB; b++) {
            bpre[z * NB + b] = acc;
            acc += bsum[z * NB + b];
        }
    }
}

__global__ void __launch_bounds__(1024)
addoff_pair_kernel(EdgePair p, int n, const int* __restrict__ bpre)
{
    int z = blockIdx.y;
    int b = blockIdx.x;
    int i = b * 1024 + threadIdx.x;
    int lane = threadIdx.x & 31;
    int wid  = threadIdx.x >> 5;
    int v = (i < n) ? p.deg[z][i] : 0;
    int x = v;
    #pragma unroll
    for (int s = 1; s < 32; s <<= 1) {
        int y = __shfl_up_sync(0xffffffffu, x, s);
        if (lane >= s) x += y;
    }
    __shared__ int ws[32];
    if (lane == 31) ws[wid] = x;
    __syncthreads();
    if (wid == 0) {
        int w = ws[lane];
        #pragma unroll
        for (int s = 1; s < 32; s <<= 1) {
            int y = __shfl_up_sync(0xffffffffu, w, s);
            if (lane >= s) w += y;
        }
        ws[lane] = w;
    }
    __syncthreads();
    int excl = x - v + (wid > 0 ? ws[wid - 1] : 0) + bpre[z * NB + b];
    if (i < n) { p.off[z][i] = excl; p.cur[z][i] = excl; }
}

__global__ void __launch_bounds__(256)
csr_pair_kernel(EdgePair p, int nE)
{
    int z = blockIdx.y;
    int e = blockIdx.x * blockDim.x + threadIdx.x;
    if (e >= nE) return;
    int pos = atomicAdd(&p.cur[z][p.dst[z][e]], 1);
    p.csr[z][pos] = p.src[z][e];
}

// ---------------------------------------------------------------------------
// Paired CSR aggregation (fp16 in/out, fp32 accumulate)
// ---------------------------------------------------------------------------
struct AggPair {
    const __half* h[2];
    const int*    csr[2];
    const int*    off[2];
    const int*    deg[2];
    __half*       agg[2];
};

__device__ __forceinline__ void acc8(float4& a0, float4& a1, const __half* p) {
    const uint2 u0 = reinterpret_cast<const uint2*>(p)[0];
    float2 f0 = __half22float2(*reinterpret_cast<const __half2*>(&u0.x));
    float2 f1 = __half22float2(*reinterpret_cast<const __half2*>(&u0.y));
    a0.x += f0.x; a0.y += f0.y; a0.z += f1.x; a0.w += f1.y;
    (void)a1;
}

__global__ void __launch_bounds__(256)
agg_pair_kernel(AggPair p, int n)
{
    int node = blockIdx.x * 8 + (threadIdx.x >> 5);
    if (node >= n) return;
    const int z = blockIdx.z;
    const __half* __restrict__ h   = p.h[z];
    const int*    __restrict__ csr = p.csr[z];
    __half*       __restrict__ agg = p.agg[z];
    int coff = blockIdx.y * 128;
    int lane = threadIdx.x & 31;
    int o = __ldg(&p.off[z][node]);
    int d = __ldg(&p.deg[z][node]);
    float4 acc = make_float4(0.f, 0.f, 0.f, 0.f);
    float4 dummy;
    int j = 0;
    for (; j + 4 <= d; j += 4) {
        int s0 = __ldg(&csr[o + j]);
        int s1 = __ldg(&csr[o + j + 1]);
        int s2 = __ldg(&csr[o + j + 2]);
        int s3 = __ldg(&csr[o + j + 3]);
        acc8(acc, dummy, h + (size_t)s0 * HDIM + coff + lane * 4);
        acc8(acc, dummy, h + (size_t)s1 * HDIM + coff + lane * 4);
        acc8(acc, dummy, h + (size_t)s2 * HDIM + coff + lane * 4);
        acc8(acc, dummy, h + (size_t)s3 * HDIM + coff + lane * 4);
    }
    for (; j < d; j++) {
        int s = __ldg(&csr[o + j]);
        acc8(acc, dummy, h + (size_t)s * HDIM + coff + lane * 4);
    }
    float sc = 1.0f / fmaxf((float)d, 1.0f);
    __half2 o0 = __floats2half2_rn(acc.x * sc, acc.y * sc);
    __half2 o1 = __floats2half2_rn(acc.z * sc, acc.w * sc);
    __half2* op = reinterpret_cast<__half2*>(agg + (size_t)node * HDIM + coff + lane * 4);
    op[0] = o0;
    op[1] = o1;
}

// ---------------------------------------------------------------------------
// Paired in-place LayerNorm (fp32 output buffer)
// ---------------------------------------------------------------------------
struct LnPair {
    float*       x[2];
    const float* g[2];
    const float* b[2];
};

__global__ void __launch_bounds__(256)
ln_pair_kernel(LnPair pp, int M)
{
    int row  = blockIdx.x * 8 + (threadIdx.x >> 5);
    int lane = threadIdx.x & 31;
    if (row >= M) return;
    const int z = blockIdx.y;
    float* p = pp.x[z] + (size_t)row * HDIM + lane * 8;
    const float* g = pp.g[z];
    const float* b = pp.b[z];
    float4 v0 = *reinterpret_cast<const float4*>(p);
    float4 v1 = *reinterpret_cast<const float4*>(p + 4);
    float s  = v0.x + v0.y + v0.z + v0.w + v1.x + v1.y + v1.z + v1.w;
    float sq = v0.x*v0.x + v0.y*v0.y + v0.z*v0.z + v0.w*v0.w
             + v1.x*v1.x + v1.y*v1.y + v1.z*v1.z + v1.w*v1.w;
    #pragma unroll
    for (int m = 16; m > 0; m >>= 1) {
        s  += __shfl_xor_sync(0xffffffffu, s,  m);
        sq += __shfl_xor_sync(0xffffffffu, sq, m);
    }
    float mu   = s * (1.0f / 256.0f);
    float var  = sq * (1.0f / 256.0f) - mu * mu;
    float rstd = rsqrtf(var + 1e-5f);
    float4 g0 = *reinterpret_cast<const float4*>(g + lane * 8);
    float4 g1 = *reinterpret_cast<const float4*>(g + lane * 8 + 4);
    float4 b0 = *reinterpret_cast<const float4*>(b + lane * 8);
    float4 b1 = *reinterpret_cast<const float4*>(b + lane * 8 + 4);
    float4 o0, o1;
    o0.x = (v0.x - mu) * rstd * g0.x + b0.x;
    o0.y = (v0.y - mu) * rstd * g0.y + b0.y;
    o0.z = (v0.z - mu) * rstd * g0.z + b0.z;
    o0.w = (v0.w - mu) * rstd * g0.w + b0.w;
    o1.x = (v1.x - mu) * rstd * g1.x + b1.x;
    o1.y = (v1.y - mu) * rstd * g1.y + b1.y;
    o1.z = (v1.z - mu) * rstd * g1.z + b1.z;
    o1.w = (v1.w - mu) * rstd * g1.w + b1.w;
    *reinterpret_cast<float4*>(p)     = o0;
    *reinterpret_cast<float4*>(p + 4) = o1;
}

// ---------------------------------------------------------------------------
// Paired fp16 tensor-core GEMM (m16n8k16, fp32 accumulate).
// 256 threads, 8 warps 2x4, warp tile 64x32. BK=32 (2 k-slices of 16).
// A [m][k] fp16 row-major; W pre-transposed [n][k] fp16.
// Both smem tiles 128 rows x 32 halves, LDH=40 (80B row stride).
// Grid: (ncol=2 fast, rowblk, side=2).
//   EPI=0: GELU -> fp16 C     EPI=1: bias only -> fp32 C
// ---------------------------------------------------------------------------
constexpr int BM   = 128;
constexpr int BK   = 32;
constexpr int LDH  = 40;                  // halves per row (pad 8)
constexpr int TILE_H = BM * LDH * 2;      // 10240 bytes
constexpr int ST   = 3;

struct GemmPair {
    const __half* A1[2];
    const __half* A2[2];
    const __half* W1[2];
    const __half* W2[2];
    const float*  bias[2];
    void*         C[2];
};

template<int K, bool HAS_A2, int EPI>
__global__ void __launch_bounds__(256, 2)
gemm_pair(GemmPair p, int M)
{
    __shared__ __half a_s[ST][BM * LDH];
    __shared__ __half b_s[ST][BM * LDH];

    constexpr int NIT = (HAS_A2 ? 2 : 1) * K / BK;

    const int zz = blockIdx.z;
    const __half* __restrict__ A1g  = p.A1[zz];
    const __half* __restrict__ A2g  = p.A2[zz];
    const __half* __restrict__ W1g  = p.W1[zz];
    const __half* __restrict__ W2g  = p.W2[zz];
    const float*  __restrict__ bias = p.bias[zz];

    const int tid  = threadIdx.x;
    const int lane = tid & 31;
    const int wid  = tid >> 5;
    const int wm   = wid >> 2;
    const int wn   = wid & 3;
    const int lq   = lane >> 2;
    const int lr   = lane & 3;
    const int row0 = blockIdx.y * BM;
    const int ncol0 = blockIdx.x * 128;

    // gmem->smem: 4 threads per row (64B), rows tid>>2 (+u*64)
    const int ar  = tid >> 2;           // 0..63
    const int ac  = (tid & 3) << 3;     // halves: 0,8,16,24

    const uint32_t a_base = (uint32_t)__cvta_generic_to_shared(a_s);
    const uint32_t b_base = (uint32_t)__cvta_generic_to_shared(b_s);

    // A ldmatrix: lanes 0-15 rows r0..r15 @k0, lanes 16-31 rows @k8
    const int row_a = lane & 15;
    const int kof_a = (lane >> 4) << 3;
    const uint32_t a_frag0 = a_base +
        (uint32_t)(((wm * 64 + row_a) * LDH + kof_a) << 1);
    // B ldmatrix: mi=lane>>3: n = (mi>>1)*8 + (lane&7), k = (mi&1)*8
    const int mi   = lane >> 3;
    const int row_b = ((mi >> 1) << 3) + (lane & 7);
    const int kof_b = (mi & 1) << 3;
    const uint32_t b_frag0 = b_base +
        (uint32_t)(((wn * 32 + row_b) * LDH + kof_b) << 1);

    float d[4][4][4];
    #pragma unroll
    for (int i = 0; i < 4; i++)
        #pragma unroll
        for (int j = 0; j < 4; j++)
            #pragma unroll
            for (int q = 0; q < 4; q++)
                d[i][j][q] = 0.f;

    auto load_stage = [&](int kt, int buf) {
        int kk = kt * BK;
        const __half* __restrict__ A  = (HAS_A2 && kk >= K) ? A2g : A1g;
        const __half* __restrict__ WT = (HAS_A2 && kk >= K) ? W2g : W1g;
        const int k0 = HAS_A2 ? (kk & (K - 1)) : kk;
        uint32_t ab = a_base + (uint32_t)(buf * TILE_H);
        uint32_t bb = b_base + (uint32_t)(buf * TILE_H);
        #pragma unroll
        for (int u = 0; u < 2; u++) {
            int r  = ar + u * 64;
            int gr = row0 + r;
            int gc = gr < M ? gr : (M - 1);
            cp16(ab + (uint32_t)((r * LDH + ac) << 1),
                 A + (size_t)gc * K + k0 + ac, gr < M);
            cp16(bb + (uint32_t)((r * LDH + ac) << 1),
                 WT + (size_t)(ncol0 + r) * K + k0 + ac, true);
        }
    };

    load_stage(0, 0);
    asm volatile("cp.async.commit_group;" ::: "memory");
    load_stage(1, 1);
    asm volatile("cp.async.commit_group;" ::: "memory");

    #pragma unroll 1
    for (int kt = 0; kt < NIT; kt++) {
        asm volatile("cp.async.wait_group 1;" ::: "memory");
        __syncthreads();
        if (kt + 2 < NIT) load_stage(kt + 2, (kt + 2) % ST);
        asm volatile("cp.async.commit_group;" ::: "memory");

        const int buf = kt % ST;
        const uint32_t af_base = a_frag0 + (uint32_t)(buf * TILE_H);
        const uint32_t bf_base = b_frag0 + (uint32_t)(buf * TILE_H);

        #pragma unroll
        for (int ks = 0; ks < 2; ks++) {           // 2 k-slices of 16
            uint32_t af[4][4];
            #pragma unroll
            for (int i = 0; i < 4; i++)
                ldsm4(af[i][0], af[i][1], af[i][2], af[i][3],
                      af_base + (uint32_t)((i * 16 * LDH + ks * 16) << 1));
            uint32_t bf[2][4];
            #pragma unroll
            for (int jj = 0; jj < 2; jj++)
                ldsm4(bf[jj][0], bf[jj][1], bf[jj][2], bf[jj][3],
                      bf_base + (uint32_t)((jj * 16 * LDH + ks * 16) << 1));
            #pragma unroll
            for (int i = 0; i < 4; i++) {
                #pragma unroll
                for (int j = 0; j < 4; j++) {
                    int jg = j >> 1, jl = j & 1;
                    mma_f16(d[i][j][0], d[i][j][1], d[i][j][2], d[i][j][3],
                            af[i][0], af[i][1], af[i][2], af[i][3],
                            bf[jg][jl * 2], bf[jg][jl * 2 + 1]);
                }
            }
        }
    }

    #pragma unroll
    for (int j = 0; j < 4; j++) {
        float2 b = *reinterpret_cast<const float2*>(bias + ncol0 + wn * 32 + j * 8 + 2 * lr);
        #pragma unroll
        for (int i = 0; i < 4; i++) {
            d[i][j][0] += b.x; d[i][j][1] += b.y;
            d[i][j][2] += b.x; d[i][j][3] += b.y;
        }
    }

    const int cbase = ncol0 + wn * 32;
    #pragma unroll
    for (int i = 0; i < 4; i++) {
        #pragma unroll
        for (int rr = 0; rr < 2; rr++) {
            int gr = row0 + wm * 64 + i * 16 + lq + rr * 8;
            if (gr < M) {
                #pragma unroll
                for (int j = 0; j < 4; j++) {
                    int col = cbase + j * 8 + 2 * lr;
                    float vx = d[i][j][rr * 2 + 0];
                    float vy = d[i][j][rr * 2 + 1];
                    if (EPI == 0) {
                        __half2 h2 = __floats2half2_rn(gelu_f(vx), gelu_f(vy));
                        *reinterpret_cast<__half2*>(
                            (__half*)p.C[zz] + (size_t)gr * HDIM + col) = h2;
                    } else {
                        float2 v = make_float2(vx, vy);
                        *reinterpret_cast<float2*>(
                            (float*)p.C[zz] + (size_t)gr * HDIM + col) = v;
                    }
                }
            }
        }
    }
}

// ---------------------------------------------------------------------------
// kernel_launch
// ---------------------------------------------------------------------------
extern "C" void kernel_launch(void* const* d_in, const int* in_sizes, int n_in,
                              void* d_out, int out_size)
{
    const float* x_user    = (const float*)d_in[0];
    const float* x_item    = (const float*)d_in[1];
    const int*   ei_ui_src = (const int*)  d_in[2];
    const int*   ei_ui_dst = (const int*)  d_in[3];
    const int*   ei_iu_src = (const int*)  d_in[4];
    const int*   ei_iu_dst = (const int*)  d_in[5];
    const float* lin_user_W = (const float*)d_in[6];
    const float* lin_user_b = (const float*)d_in[7];
    const float* lin_item_W = (const float*)d_in[8];
    const float* lin_item_b = (const float*)d_in[9];
    const float* c0_ui_Wl = (const float*)d_in[10];
    const float* c0_ui_bl = (const float*)d_in[11];
    const float* c0_ui_Wr = (const float*)d_in[12];
    const float* c0_iu_Wl = (const float*)d_in[13];
    const float* c0_iu_bl = (const float*)d_in[14];
    const float* c0_iu_Wr = (const float*)d_in[15];
    const float* c1_ui_Wl = (const float*)d_in[16];
    const float* c1_ui_bl = (const float*)d_in[17];
    const float* c1_ui_Wr = (const float*)d_in[18];
    const float* c1_iu_Wl = (const float*)d_in[19];
    const float* c1_iu_bl = (const float*)d_in[20];
    const float* c1_iu_Wr = (const float*)d_in[21];
    const float* out_user_W = (const float*)d_in[22];
    const float* out_user_b = (const float*)d_in[23];
    const float* out_item_W = (const float*)d_in[24];
    const float* out_item_b = (const float*)d_in[25];
    const float* ln_user_g  = (const float*)d_in[26];
    const float* ln_user_b2 = (const float*)d_in[27];
    const float* ln_item_g  = (const float*)d_in[28];
    const float* ln_item_b2 = (const float*)d_in[29];

    float* out = (float*)d_out;
    const int nE = in_sizes[2];
    const int M  = NNODE;

    __half *hu, *hi, *tu, *ti, *agg, *x16, *wts;
    int *deg, *off, *cur, *csr, *bsum, *bpre;
    cudaGetSymbolAddress((void**)&hu,  g_hu);
    cudaGetSymbolAddress((void**)&hi,  g_hi);
    cudaGetSymbolAddress((void**)&tu,  g_tu);
    cudaGetSymbolAddress((void**)&ti,  g_ti);
    cudaGetSymbolAddress((void**)&agg, g_agg);
    cudaGetSymbolAddress((void**)&x16, g_x16);
    cudaGetSymbolAddress((void**)&wts, g_wts);
    cudaGetSymbolAddress((void**)&deg, g_deg);
    cudaGetSymbolAddress((void**)&off, g_off);
    cudaGetSymbolAddress((void**)&cur, g_cur);
    cudaGetSymbolAddress((void**)&csr, g_csr);
    cudaGetSymbolAddress((void**)&bsum, g_bsum);
    cudaGetSymbolAddress((void**)&bpre, g_bpre);

    __half* agg0 = agg;
    __half* agg1 = agg + (size_t)M * HDIM;
    __half* xu16 = x16;
    __half* xi16 = x16 + (size_t)M * DIN;
    int *deg0 = deg,     *deg1 = deg + M;
    int *off0 = off,     *off1 = off + M;
    int *cur0 = cur,     *cur1 = cur + M;
    int *csr0 = csr,     *csr1 = csr + EDGES;

    __half* w_lin_u = wts;
    __half* w_lin_i = w_lin_u + 32768;
    __half* w_c[8];
    w_c[0] = w_lin_i + 32768;
    for (int i = 1; i < 8; i++) w_c[i] = w_c[i - 1] + 65536;
    __half* w_out_u = w_c[7] + 65536;
    __half* w_out_i = w_out_u + 65536;

    TPack tp;
    const float* twsrc[NTW] = {
        lin_user_W, lin_item_W,
        c0_ui_Wl, c0_ui_Wr, c0_iu_Wl, c0_iu_Wr,
        c1_ui_Wl, c1_ui_Wr, c1_iu_Wl, c1_iu_Wr,
        out_user_W, out_item_W };
    __half* twdst[NTW] = {
        w_lin_u, w_lin_i,
        w_c[0], w_c[1], w_c[2], w_c[3], w_c[4], w_c[5], w_c[6], w_c[7],
        w_out_u, w_out_i };
    int twK[NTW] = { DIN, DIN, HDIM, HDIM, HDIM, HDIM, HDIM, HDIM, HDIM, HDIM, HDIM, HDIM };
    for (int i = 0; i < NTW; i++) { tp.src[i] = twsrc[i]; tp.dst[i] = twdst[i]; tp.K[i] = twK[i]; }

    XPack xp;
    xp.src[0] = x_user; xp.dst[0] = xu16;
    xp.src[1] = x_item; xp.dst[1] = xi16;

    EdgePair ep;
    ep.src[0] = ei_ui_src; ep.src[1] = ei_iu_src;
    ep.dst[0] = ei_ui_dst; ep.dst[1] = ei_iu_dst;
    ep.deg[0] = deg0; ep.deg[1] = deg1;
    ep.off[0] = off0; ep.off[1] = off1;
    ep.cur[0] = cur0; ep.cur[1] = cur1;
    ep.csr[0] = csr0; ep.csr[1] = csr1;

    dim3 blk(256);
    dim3 grid_gemm(2, (M + BM - 1) / BM, 2);
    dim3 grid_edge((nE + 255) / 256, 2);
    dim3 grid_scan(NB, 2);
    dim3 grid_agg((M + 7) / 8, 2, 2);
    dim3 grid_ln((M + 7) / 8, 2);
    dim3 grid_pro(640, NTW + 4);

    auto agg_pair = [&](const __half* h0, const __half* h1) {
        AggPair ap;
        ap.h[0] = h0;   ap.h[1] = h1;
        ap.csr[0] = csr0; ap.csr[1] = csr1;
        ap.off[0] = off0; ap.off[1] = off1;
        ap.deg[0] = deg0; ap.deg[1] = deg1;
        ap.agg[0] = agg0; ap.agg[1] = agg1;
        agg_pair_kernel<<<grid_agg, blk>>>(ap, M);
    };
    auto sage_pair = [&](const __half* a1_0, const __half* a2_0, __half* wl0, __half* wr0,
                         const float* bl0, __half* c_0,
                         const __half* a1_1, const __half* a2_1, __half* wl1, __half* wr1,
                         const float* bl1, __half* c_1) {
        GemmPair gp;
        gp.A1[0] = a1_0; gp.A2[0] = a2_0; gp.W1[0] = wl0; gp.W2[0] = wr0;
        gp.bias[0] = bl0; gp.C[0] = c_0;
        gp.A1[1] = a1_1; gp.A2[1] = a2_1; gp.W1[1] = wl1; gp.W2[1] = wr1;
        gp.bias[1] = bl1; gp.C[1] = c_1;
        gemm_pair<HDIM, true, 0><<<grid_gemm, blk>>>(gp, M);
    };

    /* memset */ cudaMemsetAsync(deg, 0, 2 * M * sizeof(int));
    /* k1 */ prologue_kernel<<<grid_pro, blk>>>(tp, xp, ep, nE);
    /* k2 */ bsum_pair_kernel<<<grid_scan, blk>>>(ep, M, bsum);
    /* k3 */ bscan_kernel<<<1, 32>>>(bsum, bpre);

    /* k4: input projections (pair) — PROFILED SLOT */
    {
        GemmPair gp;
        gp.A1[0] = xu16; gp.A2[0] = nullptr; gp.W1[0] = w_lin_u; gp.W2[0] = nullptr;
        gp.bias[0] = lin_user_b; gp.C[0] = hu;
        gp.A1[1] = xi16; gp.A2[1] = nullptr; gp.W1[1] = w_lin_i; gp.W2[1] = nullptr;
        gp.bias[1] = lin_item_b; gp.C[1] = hi;
        gemm_pair<DIN, false, 0><<<grid_gemm, blk>>>(gp, M);
    }

    /* k5 */ addoff_pair_kernel<<<dim3(NB, 2), 1024>>>(ep, M, bpre);
    /* k6 */ csr_pair_kernel<<<grid_edge, blk>>>(ep, nE);

    /* k7: layer-0 aggregation (pair) */
    agg_pair(hu, hi);
    /* k8: layer-0 SAGE gemms (pair): ti, tu */
    sage_pair(agg0, hi, w_c[0], w_c[1], c0_ui_bl, ti,
              agg1, hu, w_c[2], w_c[3], c0_iu_bl, tu);

    /* k9: layer-1 aggregation (pair) */
    agg_pair(tu, ti);
    /* k10: layer-1 SAGE gemms (pair): hi, hu */
    sage_pair(agg0, ti, w_c[4], w_c[5], c1_ui_bl, hi,
              agg1, tu, w_c[6], w_c[7], c1_iu_bl, hu);

    /* k11: heads (pair, fp32 out) */
    {
        GemmPair gp;
        gp.A1[0] = hu; gp.A2[0] = nullptr; gp.W1[0] = w_out_u; gp.W2[0] = nullptr;
        gp.bias[0] = out_user_b; gp.C[0] = out;
        gp.A1[1] = hi; gp.A2[1] = nullptr; gp.W1[1] = w_out_i; gp.W2[1] = nullptr;
        gp.bias[1] = out_item_b; gp.C[1] = out + (size_t)M * HDIM;
        gemm_pair<HDIM, false, 1><<<grid_gemm, blk>>>(gp, M);
    }
    /* k12: LayerNorm (pair) */
    {
        LnPair lp;
        lp.x[0] = out;                     lp.x[1] = out + (size_t)M * HDIM;
        lp.g[0] = ln_user_g;               lp.g[1] = ln_item_g;
        lp.b[0] = ln_user_b2;              lp.b[1] = ln_item_b2;
        ln_pair_kernel<<<grid_ln, blk>>>(lp, M);
    }
}

// round 17
// speedup vs baseline: 1.6255x; 1.0123x over previous
#include <cuda_runtime.h>
#include <cuda_fp16.h>
#include <math.h>
#include <stdint.h>

#define NNODE 100000
#define EDGES 800000
#define DIN   128
#define HDIM  256
#define NB    98          // scan blocks per side

// ---------------------------------------------------------------------------
// Scratch (__device__ globals)
// ---------------------------------------------------------------------------
__device__ __half g_hu [(size_t)NNODE * HDIM];
__device__ __half g_hi [(size_t)NNODE * HDIM];
__device__ __half g_tu [(size_t)NNODE * HDIM];
__device__ __half g_ti [(size_t)NNODE * HDIM];
__device__ __half g_agg[2 * (size_t)NNODE * HDIM];
__device__ __half g_x16[2 * (size_t)NNODE * DIN];
__device__ __half g_wts[2 * 32768 + 10 * 65536];    // fp16 TRANSPOSED weights
__device__ int    g_deg[2 * NNODE];
__device__ int    g_off[2 * NNODE];
__device__ int    g_cur[2 * NNODE];
__device__ int    g_csr[2 * EDGES];
__device__ int    g_bsum[2 * NB];
__device__ int    g_bpre[2 * NB];

// ---------------------------------------------------------------------------
// Helpers
// ---------------------------------------------------------------------------
__device__ __forceinline__ float gelu_f(float x) {
    return 0.5f * x * (1.0f + erff(x * 0.70710678118654752f));
}
__device__ __forceinline__ void mma_f16(float& d0, float& d1, float& d2, float& d3,
                                        uint32_t a0, uint32_t a1, uint32_t a2, uint32_t a3,
                                        uint32_t b0, uint32_t b1)
{
    asm volatile(
        "mma.sync.aligned.m16n8k16.row.col.f32.f16.f16.f32 "
        "{%0,%1,%2,%3}, {%4,%5,%6,%7}, {%8,%9}, {%0,%1,%2,%3};"
        : "+f"(d0), "+f"(d1), "+f"(d2), "+f"(d3)
        : "r"(a0), "r"(a1), "r"(a2), "r"(a3), "r"(b0), "r"(b1));
}
__device__ __forceinline__ void cp16(uint32_t dst, const void* src, bool pred) {
    int sz = pred ? 16 : 0;
    asm volatile("cp.async.ca.shared.global [%0], [%1], 16, %2;"
                 :: "r"(dst), "l"(src), "r"(sz));
}
__device__ __forceinline__ void ldsm4(uint32_t& r0, uint32_t& r1, uint32_t& r2, uint32_t& r3,
                                      uint32_t addr)
{
    asm volatile("ldmatrix.sync.aligned.m8n8.x4.shared.b16 {%0,%1,%2,%3}, [%4];"
                 : "=r"(r0), "=r"(r1), "=r"(r2), "=r"(r3) : "r"(addr));
}

// ---------------------------------------------------------------------------
// CSR structs
// ---------------------------------------------------------------------------
struct EdgePair {
    const int* src[2];
    const int* dst[2];
    int*       deg[2];
    int*       off[2];
    int*       cur[2];
    int*       csr[2];
};

// ---------------------------------------------------------------------------
// Merged prologue: weights transpose-convert | degree count | x fp32->fp16
// ---------------------------------------------------------------------------
#define NTW 12
struct TPack { const float* src[NTW]; __half* dst[NTW]; int K[NTW]; };
struct XPack { const float* src[2]; __half* dst[2]; };

__global__ void __launch_bounds__(256)
prologue_kernel(TPack p, XPack xp, EdgePair ep, int nE)
{
    int m = blockIdx.y;
    if (m < NTW) {
        int K = p.K[m];
        int kt = (blockIdx.x & 7) * 32;
        int nt = (blockIdx.x >> 3) * 32;
        if (blockIdx.x >= 64 || kt >= K) return;
        __shared__ float tile[32][33];
        const float* __restrict__ s = p.src[m];
        __half*      __restrict__ d = p.dst[m];
        int tx = threadIdx.x & 31;
        int ty = threadIdx.x >> 5;
        #pragma unroll
        for (int u = 0; u < 4; u++) {
            int r = ty + u * 8;
            tile[r][tx] = s[(size_t)(kt + r) * 256 + nt + tx];
        }
        __syncthreads();
        #pragma unroll
        for (int u = 0; u < 4; u++) {
            int r = ty + u * 8;
            d[(size_t)(nt + r) * K + kt + tx] = __float2half_rn(tile[tx][r]);
        }
    } else if (m < NTW + 2) {
        int z = m - NTW;
        const int* __restrict__ dst = ep.dst[z];
        int* __restrict__ deg = ep.deg[z];
        for (int i = blockIdx.x * blockDim.x + threadIdx.x; i < nE;
             i += gridDim.x * blockDim.x)
            atomicAdd(&deg[dst[i]], 1);
    } else {
        int z = m - NTW - 2;
        const float4* __restrict__ s = reinterpret_cast<const float4*>(xp.src[z]);
        __half* __restrict__ d = xp.dst[z];
        int n4 = NNODE * DIN / 4;
        for (int i = blockIdx.x * blockDim.x + threadIdx.x; i < n4;
             i += gridDim.x * blockDim.x) {
            float4 v = s[i];
            __half2* o = reinterpret_cast<__half2*>(d + i * 4);
            o[0] = __floats2half2_rn(v.x, v.y);
            o[1] = __floats2half2_rn(v.z, v.w);
        }
    }
}

// ---------------------------------------------------------------------------
// Multi-block scan
// ---------------------------------------------------------------------------
__global__ void __launch_bounds__(256)
bsum_pair_kernel(EdgePair p, int n, int* __restrict__ bsum)
{
    int z = blockIdx.y;
    int b = blockIdx.x;
    int t = threadIdx.x;
    int base = b * 1024;
    int s = 0;
    #pragma unroll
    for (int u = 0; u < 4; u++) {
        int i = base + t + u * 256;
        if (i < n) s += p.deg[z][i];
    }
    #pragma unroll
    for (int m = 16; m > 0; m >>= 1) s += __shfl_xor_sync(0xffffffffu, s, m);
    __shared__ int ws[8];
    if ((t & 31) == 0) ws[t >> 5] = s;
    __syncthreads();
    if (t < 8) {
        int v = ws[t];
        #pragma unroll
        for (int m = 4; m > 0; m >>= 1) v += __shfl_xor_sync(0xffu, v, m);
        if (t == 0) bsum[z * NB + b] = v;
    }
}

__global__ void __launch_bounds__(32)
bscan_kernel(const int* __restrict__ bsum, int* __restrict__ bpre)
{
    int z = threadIdx.x;
    if (z < 2) {
        int acc = 0;
        for (int b = 0; b < NB; b++) {
            bpre[z * NB + b] = acc;
            acc += bsum[z * NB + b];
        }
    }
}

__global__ void __launch_bounds__(1024)
addoff_pair_kernel(EdgePair p, int n, const int* __restrict__ bpre)
{
    int z = blockIdx.y;
    int b = blockIdx.x;
    int i = b * 1024 + threadIdx.x;
    int lane = threadIdx.x & 31;
    int wid  = threadIdx.x >> 5;
    int v = (i < n) ? p.deg[z][i] : 0;
    int x = v;
    #pragma unroll
    for (int s = 1; s < 32; s <<= 1) {
        int y = __shfl_up_sync(0xffffffffu, x, s);
        if (lane >= s) x += y;
    }
    __shared__ int ws[32];
    if (lane == 31) ws[wid] = x;
    __syncthreads();
    if (wid == 0) {
        int w = ws[lane];
        #pragma unroll
        for (int s = 1; s < 32; s <<= 1) {
            int y = __shfl_up_sync(0xffffffffu, w, s);
            if (lane >= s) w += y;
        }
        ws[lane] = w;
    }
    __syncthreads();
    int excl = x - v + (wid > 0 ? ws[wid - 1] : 0) + bpre[z * NB + b];
    if (i < n) { p.off[z][i] = excl; p.cur[z][i] = excl; }
}

__global__ void __launch_bounds__(256)
csr_pair_kernel(EdgePair p, int nE)
{
    int z = blockIdx.y;
    int e = blockIdx.x * blockDim.x + threadIdx.x;
    if (e >= nE) return;
    int pos = atomicAdd(&p.cur[z][p.dst[z][e]], 1);
    p.csr[z][pos] = p.src[z][e];
}

// ---------------------------------------------------------------------------
// Paired CSR aggregation (fp16 in/out, fp32 accumulate)
// ---------------------------------------------------------------------------
struct AggPair {
    const __half* h[2];
    const int*    csr[2];
    const int*    off[2];
    const int*    deg[2];
    __half*       agg[2];
};

__device__ __forceinline__ void acc8(float4& a0, const __half* p) {
    const uint2 u0 = reinterpret_cast<const uint2*>(p)[0];
    float2 f0 = __half22float2(*reinterpret_cast<const __half2*>(&u0.x));
    float2 f1 = __half22float2(*reinterpret_cast<const __half2*>(&u0.y));
    a0.x += f0.x; a0.y += f0.y; a0.z += f1.x; a0.w += f1.y;
}

__global__ void __launch_bounds__(256)
agg_pair_kernel(AggPair p, int n)
{
    int node = blockIdx.x * 8 + (threadIdx.x >> 5);
    if (node >= n) return;
    const int z = blockIdx.z;
    const __half* __restrict__ h   = p.h[z];
    const int*    __restrict__ csr = p.csr[z];
    __half*       __restrict__ agg = p.agg[z];
    int coff = blockIdx.y * 128;
    int lane = threadIdx.x & 31;
    int o = __ldg(&p.off[z][node]);
    int d = __ldg(&p.deg[z][node]);
    float4 acc = make_float4(0.f, 0.f, 0.f, 0.f);
    int j = 0;
    for (; j + 4 <= d; j += 4) {
        int s0 = __ldg(&csr[o + j]);
        int s1 = __ldg(&csr[o + j + 1]);
        int s2 = __ldg(&csr[o + j + 2]);
        int s3 = __ldg(&csr[o + j + 3]);
        acc8(acc, h + (size_t)s0 * HDIM + coff + lane * 4);
        acc8(acc, h + (size_t)s1 * HDIM + coff + lane * 4);
        acc8(acc, h + (size_t)s2 * HDIM + coff + lane * 4);
        acc8(acc, h + (size_t)s3 * HDIM + coff + lane * 4);
    }
    for (; j < d; j++) {
        int s = __ldg(&csr[o + j]);
        acc8(acc, h + (size_t)s * HDIM + coff + lane * 4);
    }
    float sc = 1.0f / fmaxf((float)d, 1.0f);
    __half2 o0 = __floats2half2_rn(acc.x * sc, acc.y * sc);
    __half2 o1 = __floats2half2_rn(acc.z * sc, acc.w * sc);
    __half2* op = reinterpret_cast<__half2*>(agg + (size_t)node * HDIM + coff + lane * 4);
    op[0] = o0;
    op[1] = o1;
}

// ---------------------------------------------------------------------------
// Paired in-place LayerNorm (fp32 output buffer)
// ---------------------------------------------------------------------------
struct LnPair {
    float*       x[2];
    const float* g[2];
    const float* b[2];
};

__global__ void __launch_bounds__(256)
ln_pair_kernel(LnPair pp, int M)
{
    int row  = blockIdx.x * 8 + (threadIdx.x >> 5);
    int lane = threadIdx.x & 31;
    if (row >= M) return;
    const int z = blockIdx.y;
    float* p = pp.x[z] + (size_t)row * HDIM + lane * 8;
    const float* g = pp.g[z];
    const float* b = pp.b[z];
    float4 v0 = *reinterpret_cast<const float4*>(p);
    float4 v1 = *reinterpret_cast<const float4*>(p + 4);
    float s  = v0.x + v0.y + v0.z + v0.w + v1.x + v1.y + v1.z + v1.w;
    float sq = v0.x*v0.x + v0.y*v0.y + v0.z*v0.z + v0.w*v0.w
             + v1.x*v1.x + v1.y*v1.y + v1.z*v1.z + v1.w*v1.w;
    #pragma unroll
    for (int m = 16; m > 0; m >>= 1) {
        s  += __shfl_xor_sync(0xffffffffu, s,  m);
        sq += __shfl_xor_sync(0xffffffffu, sq, m);
    }
    float mu   = s * (1.0f / 256.0f);
    float var  = sq * (1.0f / 256.0f) - mu * mu;
    float rstd = rsqrtf(var + 1e-5f);
    float4 g0 = *reinterpret_cast<const float4*>(g + lane * 8);
    float4 g1 = *reinterpret_cast<const float4*>(g + lane * 8 + 4);
    float4 b0 = *reinterpret_cast<const float4*>(b + lane * 8);
    float4 b1 = *reinterpret_cast<const float4*>(b + lane * 8 + 4);
    float4 o0, o1;
    o0.x = (v0.x - mu) * rstd * g0.x + b0.x;
    o0.y = (v0.y - mu) * rstd * g0.y + b0.y;
    o0.z = (v0.z - mu) * rstd * g0.z + b0.z;
    o0.w = (v0.w - mu) * rstd * g0.w + b0.w;
    o1.x = (v1.x - mu) * rstd * g1.x + b1.x;
    o1.y = (v1.y - mu) * rstd * g1.y + b1.y;
    o1.z = (v1.z - mu) * rstd * g1.z + b1.z;
    o1.w = (v1.w - mu) * rstd * g1.w + b1.w;
    *reinterpret_cast<float4*>(p)     = o0;
    *reinterpret_cast<float4*>(p + 4) = o1;
}

// ---------------------------------------------------------------------------
// Paired fp16 tensor-core GEMM (m16n8k16, fp32 acc).
// ST=4 stages, stage loop unrolled x4 -> compile-time buffer offsets
// (LDSM/cp.async addresses become reg+imm; kills per-iter IADD chains).
// 256 threads, 8 warps 2x4, warp tile 64x32, BK=32, LDH=40.
// ---------------------------------------------------------------------------
constexpr int BM   = 128;
constexpr int BK   = 32;
constexpr int LDH  = 40;
constexpr int TILE_H = BM * LDH * 2;      // 10240 bytes
constexpr int ST   = 4;

struct GemmPair {
    const __half* A1[2];
    const __half* A2[2];
    const __half* W1[2];
    const __half* W2[2];
    const float*  bias[2];
    void*         C[2];
};

template<int K, bool HAS_A2, int EPI>
__global__ void __launch_bounds__(256, 2)
gemm_pair(GemmPair p, int M)
{
    __shared__ __half a_s[ST][BM * LDH];
    __shared__ __half b_s[ST][BM * LDH];

    constexpr int NIT = (HAS_A2 ? 2 : 1) * K / BK;   // 4, 8 or 16 (all %4==0)
    static_assert(NIT % 4 == 0, "NIT must be divisible by 4");

    const int zz = blockIdx.z;
    const __half* __restrict__ A1g  = p.A1[zz];
    const __half* __restrict__ A2g  = p.A2[zz];
    const __half* __restrict__ W1g  = p.W1[zz];
    const __half* __restrict__ W2g  = p.W2[zz];
    const float*  __restrict__ bias = p.bias[zz];

    const int tid  = threadIdx.x;
    const int lane = tid & 31;
    const int wid  = tid >> 5;
    const int wm   = wid >> 2;
    const int wn   = wid & 3;
    const int lq   = lane >> 2;
    const int lr   = lane & 3;
    const int row0 = blockIdx.y * BM;
    const int ncol0 = blockIdx.x * 128;

    const int ar  = tid >> 2;
    const int ac  = (tid & 3) << 3;

    const uint32_t a_base = (uint32_t)__cvta_generic_to_shared(a_s);
    const uint32_t b_base = (uint32_t)__cvta_generic_to_shared(b_s);

    const int row_a = lane & 15;
    const int kof_a = (lane >> 4) << 3;
    const uint32_t a_frag0 = a_base +
        (uint32_t)(((wm * 64 + row_a) * LDH + kof_a) << 1);
    const int mi   = lane >> 3;
    const int row_b = ((mi >> 1) << 3) + (lane & 7);
    const int kof_b = (mi & 1) << 3;
    const uint32_t b_frag0 = b_base +
        (uint32_t)(((wn * 32 + row_b) * LDH + kof_b) << 1);

    float d[4][4][4];
    #pragma unroll
    for (int i = 0; i < 4; i++)
        #pragma unroll
        for (int j = 0; j < 4; j++)
            #pragma unroll
            for (int q = 0; q < 4; q++)
                d[i][j][q] = 0.f;

    auto load_stage = [&](int kt, uint32_t ab, uint32_t bb) {
        int kk = kt * BK;
        const __half* __restrict__ A  = (HAS_A2 && kk >= K) ? A2g : A1g;
        const __half* __restrict__ WT = (HAS_A2 && kk >= K) ? W2g : W1g;
        const int k0 = HAS_A2 ? (kk & (K - 1)) : kk;
        #pragma unroll
        for (int u = 0; u < 2; u++) {
            int r  = ar + u * 64;
            int gr = row0 + r;
            int gc = gr < M ? gr : (M - 1);
            cp16(ab + (uint32_t)((r * LDH + ac) << 1),
                 A + (size_t)gc * K + k0 + ac, gr < M);
            cp16(bb + (uint32_t)((r * LDH + ac) << 1),
                 WT + (size_t)(ncol0 + r) * K + k0 + ac, true);
        }
    };

    load_stage(0, a_base, b_base);
    asm volatile("cp.async.commit_group;" ::: "memory");
    load_stage(1, a_base + TILE_H, b_base + TILE_H);
    asm volatile("cp.async.commit_group;" ::: "memory");
    load_stage(2, a_base + 2 * TILE_H, b_base + 2 * TILE_H);
    asm volatile("cp.async.commit_group;" ::: "memory");

    #pragma unroll 1
    for (int kt4 = 0; kt4 < NIT; kt4 += 4) {
        #pragma unroll
        for (int s = 0; s < 4; s++) {          // s compile-time after unroll
            const int kt = kt4 + s;
            asm volatile("cp.async.wait_group 2;" ::: "memory");
            __syncthreads();
            {
                constexpr int LB = 0;          // dummy to keep scope tidy
                (void)LB;
            }
            const int ldbuf = (s + 3) & 3;     // compile-time
            if (kt + 3 < NIT)
                load_stage(kt + 3,
                           a_base + (uint32_t)(ldbuf * TILE_H),
                           b_base + (uint32_t)(ldbuf * TILE_H));
            asm volatile("cp.async.commit_group;" ::: "memory");

            const uint32_t af_base = a_frag0 + (uint32_t)(s * TILE_H);
            const uint32_t bf_base = b_frag0 + (uint32_t)(s * TILE_H);

            #pragma unroll
            for (int ks = 0; ks < 2; ks++) {
                uint32_t af[4][4];
                #pragma unroll
                for (int i = 0; i < 4; i++)
                    ldsm4(af[i][0], af[i][1], af[i][2], af[i][3],
                          af_base + (uint32_t)((i * 16 * LDH + ks * 16) << 1));
                uint32_t bf[2][4];
                #pragma unroll
                for (int jj = 0; jj < 2; jj++)
                    ldsm4(bf[jj][0], bf[jj][1], bf[jj][2], bf[jj][3],
                          bf_base + (uint32_t)((jj * 16 * LDH + ks * 16) << 1));
                #pragma unroll
                for (int i = 0; i < 4; i++) {
                    #pragma unroll
                    for (int j = 0; j < 4; j++) {
                        int jg = j >> 1, jl = j & 1;
                        mma_f16(d[i][j][0], d[i][j][1], d[i][j][2], d[i][j][3],
                                af[i][0], af[i][1], af[i][2], af[i][3],
                                bf[jg][jl * 2], bf[jg][jl * 2 + 1]);
                    }
                }
            }
        }
    }

    #pragma unroll
    for (int j = 0; j < 4; j++) {
        float2 b = *reinterpret_cast<const float2*>(bias + ncol0 + wn * 32 + j * 8 + 2 * lr);
        #pragma unroll
        for (int i = 0; i < 4; i++) {
            d[i][j][0] += b.x; d[i][j][1] += b.y;
            d[i][j][2] += b.x; d[i][j][3] += b.y;
        }
    }

    const int cbase = ncol0 + wn * 32;
    #pragma unroll
    for (int i = 0; i < 4; i++) {
        #pragma unroll
        for (int rr = 0; rr < 2; rr++) {
            int gr = row0 + wm * 64 + i * 16 + lq + rr * 8;
            if (gr < M) {
                #pragma unroll
                for (int j = 0; j < 4; j++) {
                    int col = cbase + j * 8 + 2 * lr;
                    float vx = d[i][j][rr * 2 + 0];
                    float vy = d[i][j][rr * 2 + 1];
                    if (EPI == 0) {
                        __half2 h2 = __floats2half2_rn(gelu_f(vx), gelu_f(vy));
                        *reinterpret_cast<__half2*>(
                            (__half*)p.C[zz] + (size_t)gr * HDIM + col) = h2;
                    } else {
                        float2 v = make_float2(vx, vy);
                        *reinterpret_cast<float2*>(
                            (float*)p.C[zz] + (size_t)gr * HDIM + col) = v;
                    }
                }
            }
        }
    }
}

// ---------------------------------------------------------------------------
// kernel_launch
// ---------------------------------------------------------------------------
extern "C" void kernel_launch(void* const* d_in, const int* in_sizes, int n_in,
                              void* d_out, int out_size)
{
    const float* x_user    = (const float*)d_in[0];
    const float* x_item    = (const float*)d_in[1];
    const int*   ei_ui_src = (const int*)  d_in[2];
    const int*   ei_ui_dst = (const int*)  d_in[3];
    const int*   ei_iu_src = (const int*)  d_in[4];
    const int*   ei_iu_dst = (const int*)  d_in[5];
    const float* lin_user_W = (const float*)d_in[6];
    const float* lin_user_b = (const float*)d_in[7];
    const float* lin_item_W = (const float*)d_in[8];
    const float* lin_item_b = (const float*)d_in[9];
    const float* c0_ui_Wl = (const float*)d_in[10];
    const float* c0_ui_bl = (const float*)d_in[11];
    const float* c0_ui_Wr = (const float*)d_in[12];
    const float* c0_iu_Wl = (const float*)d_in[13];
    const float* c0_iu_bl = (const float*)d_in[14];
    const float* c0_iu_Wr = (const float*)d_in[15];
    const float* c1_ui_Wl = (const float*)d_in[16];
    const float* c1_ui_bl = (const float*)d_in[17];
    const float* c1_ui_Wr = (const float*)d_in[18];
    const float* c1_iu_Wl = (const float*)d_in[19];
    const float* c1_iu_bl = (const float*)d_in[20];
    const float* c1_iu_Wr = (const float*)d_in[21];
    const float* out_user_W = (const float*)d_in[22];
    const float* out_user_b = (const float*)d_in[23];
    const float* out_item_W = (const float*)d_in[24];
    const float* out_item_b = (const float*)d_in[25];
    const float* ln_user_g  = (const float*)d_in[26];
    const float* ln_user_b2 = (const float*)d_in[27];
    const float* ln_item_g  = (const float*)d_in[28];
    const float* ln_item_b2 = (const float*)d_in[29];

    float* out = (float*)d_out;
    const int nE = in_sizes[2];
    const int M  = NNODE;

    __half *hu, *hi, *tu, *ti, *agg, *x16, *wts;
    int *deg, *off, *cur, *csr, *bsum, *bpre;
    cudaGetSymbolAddress((void**)&hu,  g_hu);
    cudaGetSymbolAddress((void**)&hi,  g_hi);
    cudaGetSymbolAddress((void**)&tu,  g_tu);
    cudaGetSymbolAddress((void**)&ti,  g_ti);
    cudaGetSymbolAddress((void**)&agg, g_agg);
    cudaGetSymbolAddress((void**)&x16, g_x16);
    cudaGetSymbolAddress((void**)&wts, g_wts);
    cudaGetSymbolAddress((void**)&deg, g_deg);
    cudaGetSymbolAddress((void**)&off, g_off);
    cudaGetSymbolAddress((void**)&cur, g_cur);
    cudaGetSymbolAddress((void**)&csr, g_csr);
    cudaGetSymbolAddress((void**)&bsum, g_bsum);
    cudaGetSymbolAddress((void**)&bpre, g_bpre);

    __half* agg0 = agg;
    __half* agg1 = agg + (size_t)M * HDIM;
    __half* xu16 = x16;
    __half* xi16 = x16 + (size_t)M * DIN;
    int *deg0 = deg,     *deg1 = deg + M;
    int *off0 = off,     *off1 = off + M;
    int *cur0 = cur,     *cur1 = cur + M;
    int *csr0 = csr,     *csr1 = csr + EDGES;

    __half* w_lin_u = wts;
    __half* w_lin_i = w_lin_u + 32768;
    __half* w_c[8];
    w_c[0] = w_lin_i + 32768;
    for (int i = 1; i < 8; i++) w_c[i] = w_c[i - 1] + 65536;
    __half* w_out_u = w_c[7] + 65536;
    __half* w_out_i = w_out_u + 65536;

    TPack tp;
    const float* twsrc[NTW] = {
        lin_user_W, lin_item_W,
        c0_ui_Wl, c0_ui_Wr, c0_iu_Wl, c0_iu_Wr,
        c1_ui_Wl, c1_ui_Wr, c1_iu_Wl, c1_iu_Wr,
        out_user_W, out_item_W };
    __half* twdst[NTW] = {
        w_lin_u, w_lin_i,
        w_c[0], w_c[1], w_c[2], w_c[3], w_c[4], w_c[5], w_c[6], w_c[7],
        w_out_u, w_out_i };
    int twK[NTW] = { DIN, DIN, HDIM, HDIM, HDIM, HDIM, HDIM, HDIM, HDIM, HDIM, HDIM, HDIM };
    for (int i = 0; i < NTW; i++) { tp.src[i] = twsrc[i]; tp.dst[i] = twdst[i]; tp.K[i] = twK[i]; }

    XPack xp;
    xp.src[0] = x_user; xp.dst[0] = xu16;
    xp.src[1] = x_item; xp.dst[1] = xi16;

    EdgePair ep;
    ep.src[0] = ei_ui_src; ep.src[1] = ei_iu_src;
    ep.dst[0] = ei_ui_dst; ep.dst[1] = ei_iu_dst;
    ep.deg[0] = deg0; ep.deg[1] = deg1;
    ep.off[0] = off0; ep.off[1] = off1;
    ep.cur[0] = cur0; ep.cur[1] = cur1;
    ep.csr[0] = csr0; ep.csr[1] = csr1;

    dim3 blk(256);
    dim3 grid_gemm(2, (M + BM - 1) / BM, 2);
    dim3 grid_edge((nE + 255) / 256, 2);
    dim3 grid_scan(NB, 2);
    dim3 grid_agg((M + 7) / 8, 2, 2);
    dim3 grid_ln((M + 7) / 8, 2);
    dim3 grid_pro(640, NTW + 4);

    auto agg_pair = [&](const __half* h0, const __half* h1) {
        AggPair ap;
        ap.h[0] = h0;   ap.h[1] = h1;
        ap.csr[0] = csr0; ap.csr[1] = csr1;
        ap.off[0] = off0; ap.off[1] = off1;
        ap.deg[0] = deg0; ap.deg[1] = deg1;
        ap.agg[0] = agg0; ap.agg[1] = agg1;
        agg_pair_kernel<<<grid_agg, blk>>>(ap, M);
    };
    auto sage_pair = [&](const __half* a1_0, const __half* a2_0, __half* wl0, __half* wr0,
                         const float* bl0, __half* c_0,
                         const __half* a1_1, const __half* a2_1, __half* wl1, __half* wr1,
                         const float* bl1, __half* c_1) {
        GemmPair gp;
        gp.A1[0] = a1_0; gp.A2[0] = a2_0; gp.W1[0] = wl0; gp.W2[0] = wr0;
        gp.bias[0] = bl0; gp.C[0] = c_0;
        gp.A1[1] = a1_1; gp.A2[1] = a2_1; gp.W1[1] = wl1; gp.W2[1] = wr1;
        gp.bias[1] = bl1; gp.C[1] = c_1;
        gemm_pair<HDIM, true, 0><<<grid_gemm, blk>>>(gp, M);
    };

    /* memset */ cudaMemsetAsync(deg, 0, 2 * M * sizeof(int));
    /* k1 */ prologue_kernel<<<grid_pro, blk>>>(tp, xp, ep, nE);
    /* k2 */ bsum_pair_kernel<<<grid_scan, blk>>>(ep, M, bsum);
    /* k3 */ bscan_kernel<<<1, 32>>>(bsum, bpre);

    /* k4: input projections (pair) — PROFILED SLOT */
    {
        GemmPair gp;
        gp.A1[0] = xu16; gp.A2[0] = nullptr; gp.W1[0] = w_lin_u; gp.W2[0] = nullptr;
        gp.bias[0] = lin_user_b; gp.C[0] = hu;
        gp.A1[1] = xi16; gp.A2[1] = nullptr; gp.W1[1] = w_lin_i; gp.W2[1] = nullptr;
        gp.bias[1] = lin_item_b; gp.C[1] = hi;
        gemm_pair<DIN, false, 0><<<grid_gemm, blk>>>(gp, M);
    }

    /* k5 */ addoff_pair_kernel<<<dim3(NB, 2), 1024>>>(ep, M, bpre);
    /* k6 */ csr_pair_kernel<<<grid_edge, blk>>>(ep, nE);

    /* k7: layer-0 aggregation (pair) */
    agg_pair(hu, hi);
    /* k8: layer-0 SAGE gemms (pair): ti, tu */
    sage_pair(agg0, hi, w_c[0], w_c[1], c0_ui_bl, ti,
              agg1, hu, w_c[2], w_c[3], c0_iu_bl, tu);

    /* k9: layer-1 aggregation (pair) */
    agg_pair(tu, ti);
    /* k10: layer-1 SAGE gemms (pair): hi, hu */
    sage_pair(agg0, ti, w_c[4], w_c[5], c1_ui_bl, hi,
              agg1, tu, w_c[6], w_c[7], c1_iu_bl, hu);

    /* k11: heads (pair, fp32 out) */
    {
        GemmPair gp;
        gp.A1[0] = hu; gp.A2[0] = nullptr; gp.W1[0] = w_out_u; gp.W2[0] = nullptr;
        gp.bias[0] = out_user_b; gp.C[0] = out;
        gp.A1[1] = hi; gp.A2[1] = nullptr; gp.W1[1] = w_out_i; gp.W2[1] = nullptr;
        gp.bias[1] = out_item_b; gp.C[1] = out + (size_t)M * HDIM;
        gemm_pair<HDIM, false, 1><<<grid_gemm, blk>>>(gp, M);
    }
    /* k12: LayerNorm (pair) */
    {
        LnPair lp;
        lp.x[0] = out;                     lp.x[1] = out + (size_t)M * HDIM;
        lp.g[0] = ln_user_g;               lp.g[1] = ln_item_g;
        lp.b[0] = ln_user_b2;              lp.b[1] = ln_item_b2;
        ln_pair_kernel<<<grid_ln, blk>>>(lp, M);
    }
}